// round 10
// baseline (speedup 1.0000x reference)
#include <cuda_runtime.h>
#include <cstdint>

#define Tn 2048

__device__ __forceinline__ uint32_t smem_u32(const void* p) {
    return (uint32_t)__cvta_generic_to_shared(p);
}
__device__ __forceinline__ void cluster_sync_() {
    asm volatile("barrier.cluster.arrive.aligned;" ::: "memory");
    asm volatile("barrier.cluster.wait.aligned;" ::: "memory");
}
__device__ __forceinline__ uint32_t mapa_sh(uint32_t addr, uint32_t rank) {
    uint32_t r;
    asm("mapa.shared::cluster.u32 %0, %1, %2;" : "=r"(r) : "r"(addr), "r"(rank));
    return r;
}
__device__ __forceinline__ void mbar_init(uint32_t a, uint32_t cnt) {
    asm volatile("mbarrier.init.shared.b64 [%0], %1;" :: "r"(a), "r"(cnt) : "memory");
}
__device__ __forceinline__ void mbar_arm_tx(uint32_t a, uint32_t tx) {
    asm volatile("mbarrier.arrive.expect_tx.shared.b64 _, [%0], %1;"
                 :: "r"(a), "r"(tx) : "memory");
}
__device__ __forceinline__ void mbar_wait_cl(uint32_t a, uint32_t parity) {
    asm volatile(
        "{\n\t.reg .pred P;\n\t"
        "WL_%=:\n\t"
        "mbarrier.try_wait.parity.acquire.cluster.shared::cta.b64 P, [%0], %1, 0x989680;\n\t"
        "@P bra.uni WD_%=;\n\t"
        "bra.uni WL_%=;\n\t"
        "WD_%=:\n\t}"
        :: "r"(a), "r"(parity) : "memory");
}
__device__ __forceinline__ void bulk_dsmem(uint32_t dst, uint32_t src,
                                           uint32_t bytes, uint32_t mbar) {
    asm volatile(
        "cp.async.bulk.shared::cluster.shared::cta.mbarrier::complete_tx::bytes "
        "[%0], [%1], %2, [%3];"
        :: "r"(dst), "r"(src), "r"(bytes), "r"(mbar) : "memory");
}
__device__ __forceinline__ void fence_async_() {
    asm volatile("fence.proxy.async.shared::cta;" ::: "memory");
}
__device__ __forceinline__ float sigm(float v) { return 1.0f / (1.0f + __expf(-v)); }
__device__ __forceinline__ float tanh_(float v) { return 2.0f / (1.0f + __expf(-2.0f * v)) - 1.0f; }

__device__ __forceinline__ unsigned long long pk2(float v) {
    unsigned long long r;
    asm("mov.b64 %0, {%1, %1};" : "=l"(r) : "f"(v));
    return r;
}
__device__ __forceinline__ void ffma2(unsigned long long& d, unsigned long long a,
                                      unsigned long long b) {
    asm("fma.rn.f32x2 %0, %1, %2, %0;" : "+l"(d) : "l"(a), "l"(b));
}
__device__ __forceinline__ void unpk(unsigned long long v, float& lo, float& hi) {
    asm("mov.b64 {%0, %1}, %2;" : "=f"(lo), "=f"(hi) : "l"(v));
}
__device__ __forceinline__ float sel4(float4 v, int s) {
    return (s == 0) ? v.x : (s == 1) ? v.y : (s == 2) ? v.z : v.w;
}

// ---------------------------------------------------------------------------
// FUSED both-layers kernel: cluster of 4 CTAs x 512 threads, 8 batches per
// cluster, 32 clusters = 128 CTAs. Each CTA owns hidden-slice 32 of BOTH
// layers (128 gate rows each). Per step t:
//   L0 compute (h1(t-1), seg 0..7 x 16 j)  -> bar1 -> L0 combine -> h1(t)
//   bulk-exchange; seg>=4: wait h2(t-1), W_hh1 compute; seg<4: wait h1(t),
//   W_ih1 compute -> bar2 -> L1 combine -> h2(t) exchange (hidden under the
//   next step's L0 phase). h1 never touches gmem.
// mbar phases: both nets waited at step t with parity (t>>1)&1; h2 buffer 1
// primed with a zero pre-exchange.
// smem floats:
//   [0..7]   mbar1[2] @bytes 0,8; mbar2[2] @bytes 16,24
//   hb1 [2][128 j][8 b]  @8      (2048)
//   hb2 [2][128 j][8 b]  @2056   (2048)
//   st1 [2][256]         @4104   (512)
//   st2 [2][256]         @4616   (512)
//   xbf [2][5][8]        @5128   (80)
//   gb0 [2][8][128][9]   @5208   (18432)
//   gb1 [8][128][9]      @23640  (9216)
//   wxs [128][5]         @32856  (640)
//   bb0 [128]            @33496, bb1 [128] @33624 -> total 33752 f = 135 KB
// ---------------------------------------------------------------------------
#define HB1 8
#define HB2 2056
#define ST1 4104
#define ST2 4616
#define XBF 5128
#define GB0 5208
#define GB1 23640
#define WXS 32856
#define BB0 33496
#define BB1 33624
#define SMEM_BYTES (33752 * 4)

__global__ void __cluster_dims__(4, 1, 1) __launch_bounds__(512, 1)
lstm_fused(const float* __restrict__ x,
           const float* __restrict__ Wih0, const float* __restrict__ Whh0,
           const float* __restrict__ bih0, const float* __restrict__ bhh0,
           const float* __restrict__ Wih1, const float* __restrict__ Whh1,
           const float* __restrict__ bih1, const float* __restrict__ bhh1,
           const float* __restrict__ fcW, const float* __restrict__ fcb,
           float* __restrict__ out)
{
    extern __shared__ float sm[];
    const uint32_t smb = smem_u32(sm);
    float* hb1 = sm + HB1;
    float* hb2 = sm + HB2;
    float* st1 = sm + ST1;
    float* st2 = sm + ST2;
    float* xbf = sm + XBF;
    float* gb0 = sm + GB0;
    float* gb1 = sm + GB1;
    float* wxs = sm + WXS;
    float* bb0 = sm + BB0;
    float* bb1 = sm + BB1;

    const int tid  = threadIdx.x;
    const int rank = blockIdx.x & 3;
    const int b0   = (blockIdx.x >> 2) * 8;

    const int seg = tid >> 6;            // 0..7 (constant within a warp)
    const int rp  = tid & 63;
    const int r0  = rp, r1 = rp + 64;    // two gate rows per thread
    const int gr0 = ((r0 >> 5) << 7) + (rank << 5) + (r0 & 31);
    const int gr1 = ((r1 >> 5) << 7) + (rank << 5) + (r1 & 31);

    // L0 weights: Whh0, 16 j per seg, 2 rows (32 floats)
    float4 v0a[4], v0b[4];
    {
        const float4* s0 = (const float4*)(Whh0 + gr0 * 128 + seg * 16);
        const float4* s1 = (const float4*)(Whh0 + gr1 * 128 + seg * 16);
        #pragma unroll
        for (int kk = 0; kk < 4; ++kk) { v0a[kk] = s0[kk]; v0b[kk] = s1[kk]; }
    }
    // L1 weights: seg<4 -> Wih1, seg>=4 -> Whh1; 32 j per seg, 2 rows (64 f)
    float4 v1a[8], v1b[8];
    {
        const float* wm = (seg < 4) ? Wih1 : Whh1;
        const float4* s0 = (const float4*)(wm + gr0 * 128 + (seg & 3) * 32);
        const float4* s1 = (const float4*)(wm + gr1 * 128 + (seg & 3) * 32);
        #pragma unroll
        for (int kk = 0; kk < 8; ++kk) { v1a[kk] = s0[kk]; v1b[kk] = s1[kk]; }
    }

    if (tid == 0) {
        mbar_init(smb + 0, 1);  mbar_init(smb + 8, 1);
        mbar_init(smb + 16, 1); mbar_init(smb + 24, 1);
        mbar_arm_tx(smb + 0, 4096);  mbar_arm_tx(smb + 8, 4096);
        mbar_arm_tx(smb + 16, 4096); mbar_arm_tx(smb + 24, 4096);
    }
    if (tid < 128) {   // smem bias / Wih0 tables for this CTA's 128 rows
        int gr = ((tid >> 5) << 7) + (rank << 5) + (tid & 31);
        bb0[tid] = bih0[gr] + bhh0[gr];
        bb1[tid] = bih1[gr] + bhh1[gr];
        #pragma unroll
        for (int d = 0; d < 5; ++d) wxs[tid * 5 + d] = Wih0[gr * 5 + d];
    }
    for (int i = tid; i < 1024; i += 512) hb1[1024 + i] = 0.f;  // h1(-1)=0
    if (tid < 256) st2[256 + tid] = 0.f;                        // h2(-1) stage
    if (tid < 40) {
        int b = tid / 5, d = tid % 5;
        xbf[d * 8 + b] = x[((size_t)(b0 + b) * Tn) * 5 + d];
    }

    const int cb = tid & 7, cj = (tid >> 3) & 31;   // combine map (tid<256)
    uint32_t base[4];
    #pragma unroll
    for (int r = 0; r < 4; ++r) base[r] = mapa_sh(smb, r);

    __syncthreads();
    cluster_sync_();   // mbarriers armed + zeroed buffers visible cluster-wide
    if (tid < 4) {     // prime h2 buffer 1: zero exchange into mbar2[1]
        fence_async_();
        bulk_dsmem(base[tid] + (HB2 + 1024 + rank * 256) * 4,
                   smb + (ST2 + 256) * 4, 1024, base[tid] + 24);
    }

    float c0 = 0.f, c1 = 0.f;
    unsigned long long a0[4], a1[4];

    for (int t = 0; t < Tn; ++t) {
        const int par = t & 1, nb = par ^ 1;
        float pre = 0.f;
        if (tid < 40 && t + 1 < Tn) {
            int b = tid / 5, d = tid % 5;
            pre = x[((size_t)(b0 + b) * Tn + (t + 1)) * 5 + d];
        }

        // ---- L0 compute over h1(t-1) (buffer nb) ----
        #pragma unroll
        for (int i = 0; i < 4; ++i) { a0[i] = 0ull; a1[i] = 0ull; }
        {
            const float* src = hb1 + nb * 1024 + seg * 128;
            #pragma unroll
            for (int kk = 0; kk < 4; ++kk) {
                float4 w0v = v0a[kk], w1v = v0b[kk];
                #pragma unroll
                for (int s = 0; s < 4; ++s) {
                    const float* p = src + (kk * 4 + s) * 8;
                    ulonglong2 h0 = *(const ulonglong2*)(p);
                    ulonglong2 h1v = *(const ulonglong2*)(p + 4);
                    unsigned long long p0 = pk2(sel4(w0v, s));
                    ffma2(a0[0], p0, h0.x); ffma2(a0[1], p0, h0.y);
                    ffma2(a0[2], p0, h1v.x); ffma2(a0[3], p0, h1v.y);
                    unsigned long long p1 = pk2(sel4(w1v, s));
                    ffma2(a1[0], p1, h0.x); ffma2(a1[1], p1, h0.y);
                    ffma2(a1[2], p1, h1v.x); ffma2(a1[3], p1, h1v.y);
                }
            }
        }
        if (seg == 0) {   // x-projection (weights from smem)
            const float* xb = xbf + par * 40;
            #pragma unroll
            for (int d = 0; d < 5; ++d) {
                unsigned long long x01 = *(const unsigned long long*)(xb + d * 8);
                unsigned long long x23 = *(const unsigned long long*)(xb + d * 8 + 2);
                unsigned long long x45 = *(const unsigned long long*)(xb + d * 8 + 4);
                unsigned long long x67 = *(const unsigned long long*)(xb + d * 8 + 6);
                unsigned long long p0 = pk2(wxs[r0 * 5 + d]);
                ffma2(a0[0], p0, x01); ffma2(a0[1], p0, x23);
                ffma2(a0[2], p0, x45); ffma2(a0[3], p0, x67);
                unsigned long long p1 = pk2(wxs[r1 * 5 + d]);
                ffma2(a1[0], p1, x01); ffma2(a1[1], p1, x23);
                ffma2(a1[2], p1, x45); ffma2(a1[3], p1, x67);
            }
        }
        {   // L0 gate partials, pitch 9 (conflict-free)
            float* gp = gb0 + par * 9216 + seg * 1152;
            float v0, v1;
            #pragma unroll
            for (int i = 0; i < 4; ++i) {
                unpk(a0[i], v0, v1);
                gp[r0 * 9 + i * 2] = v0; gp[r0 * 9 + i * 2 + 1] = v1;
            }
            #pragma unroll
            for (int i = 0; i < 4; ++i) {
                unpk(a1[i], v0, v1);
                gp[r1 * 9 + i * 2] = v0; gp[r1 * 9 + i * 2 + 1] = v1;
            }
        }
        if (tid < 40 && t + 1 < Tn) {
            int b = tid / 5, d = tid % 5;
            xbf[nb * 40 + d * 8 + b] = pre;
        }
        __syncthreads();   // bar1: gb0 ready

        if (tid < 256) {   // ---- L0 combine -> h1(t), launch exchange ----
            const float* gq = gb0 + par * 9216;
            float gv[4];
            #pragma unroll
            for (int g = 0; g < 4; ++g) {
                int r = g * 32 + cj;
                float s = bb0[r];
                #pragma unroll
                for (int sg = 0; sg < 8; ++sg) s += gq[sg * 1152 + r * 9 + cb];
                gv[g] = s;
            }
            float ii = sigm(gv[0]), ff = sigm(gv[1]), g = tanh_(gv[2]), oo = sigm(gv[3]);
            c0 = fmaf(ff, c0, ii * g);
            float h = oo * tanh_(c0);
            st1[par * 256 + tid] = h;
            __syncwarp();
            if ((tid & 31) < 4) {
                int dr = tid & 31;
                fence_async_();
                bulk_dsmem(base[dr] + (HB1 + par * 1024 + rank * 256 + (tid & 224)) * 4,
                           smb + (ST1 + par * 256 + (tid & 224)) * 4, 128,
                           base[dr] + par * 8);               // mbar1[par]
            }
        }

        // ---- L1 compute: seg>=4 over h2(t-1), seg<4 over h1(t) ----
        #pragma unroll
        for (int i = 0; i < 4; ++i) { a0[i] = 0ull; a1[i] = 0ull; }
        if (tid >= 256) {
            mbar_wait_cl(smb + 16 + nb * 8, (t >> 1) & 1);    // h2(t-1)
            if (tid == 256) mbar_arm_tx(smb + 16 + nb * 8, 4096);
            const float* src = hb2 + nb * 1024 + (seg & 3) * 256;
            #pragma unroll
            for (int kk = 0; kk < 8; ++kk) {
                float4 w0v = v1a[kk], w1v = v1b[kk];
                #pragma unroll
                for (int s = 0; s < 4; ++s) {
                    const float* p = src + (kk * 4 + s) * 8;
                    ulonglong2 h0 = *(const ulonglong2*)(p);
                    ulonglong2 h1v = *(const ulonglong2*)(p + 4);
                    unsigned long long p0 = pk2(sel4(w0v, s));
                    ffma2(a0[0], p0, h0.x); ffma2(a0[1], p0, h0.y);
                    ffma2(a0[2], p0, h1v.x); ffma2(a0[3], p0, h1v.y);
                    unsigned long long p1 = pk2(sel4(w1v, s));
                    ffma2(a1[0], p1, h0.x); ffma2(a1[1], p1, h0.y);
                    ffma2(a1[2], p1, h1v.x); ffma2(a1[3], p1, h1v.y);
                }
            }
        } else {
            mbar_wait_cl(smb + par * 8, (t >> 1) & 1);        // h1(t)
            if (tid == 0) mbar_arm_tx(smb + par * 8, 4096);
            const float* src = hb1 + par * 1024 + seg * 256;
            #pragma unroll
            for (int kk = 0; kk < 8; ++kk) {
                float4 w0v = v1a[kk], w1v = v1b[kk];
                #pragma unroll
                for (int s = 0; s < 4; ++s) {
                    const float* p = src + (kk * 4 + s) * 8;
                    ulonglong2 h0 = *(const ulonglong2*)(p);
                    ulonglong2 h1v = *(const ulonglong2*)(p + 4);
                    unsigned long long p0 = pk2(sel4(w0v, s));
                    ffma2(a0[0], p0, h0.x); ffma2(a0[1], p0, h0.y);
                    ffma2(a0[2], p0, h1v.x); ffma2(a0[3], p0, h1v.y);
                    unsigned long long p1 = pk2(sel4(w1v, s));
                    ffma2(a1[0], p1, h0.x); ffma2(a1[1], p1, h0.y);
                    ffma2(a1[2], p1, h1v.x); ffma2(a1[3], p1, h1v.y);
                }
            }
        }
        {   // L1 gate partials, pitch 9
            float* gp = gb1 + seg * 1152;
            float v0, v1;
            #pragma unroll
            for (int i = 0; i < 4; ++i) {
                unpk(a0[i], v0, v1);
                gp[r0 * 9 + i * 2] = v0; gp[r0 * 9 + i * 2 + 1] = v1;
            }
            #pragma unroll
            for (int i = 0; i < 4; ++i) {
                unpk(a1[i], v0, v1);
                gp[r1 * 9 + i * 2] = v0; gp[r1 * 9 + i * 2 + 1] = v1;
            }
        }
        __syncthreads();   // bar2: gb1 ready

        if (tid < 256) {   // ---- L1 combine -> h2(t), launch exchange ----
            float gv[4];
            #pragma unroll
            for (int g = 0; g < 4; ++g) {
                int r = g * 32 + cj;
                float s = bb1[r];
                #pragma unroll
                for (int sg = 0; sg < 8; ++sg) s += gb1[sg * 1152 + r * 9 + cb];
                gv[g] = s;
            }
            float ii = sigm(gv[0]), ff = sigm(gv[1]), g = tanh_(gv[2]), oo = sigm(gv[3]);
            c1 = fmaf(ff, c1, ii * g);
            float h = oo * tanh_(c1);
            st2[par * 256 + tid] = h;
            __syncwarp();
            if ((tid & 31) < 4) {
                int dr = tid & 31;
                fence_async_();
                bulk_dsmem(base[dr] + (HB2 + par * 1024 + rank * 256 + (tid & 224)) * 4,
                           smb + (ST2 + par * 256 + (tid & 224)) * 4, 128,
                           base[dr] + 16 + par * 8);          // mbar2[par]
            }
        }
    }
    // consume the final h2 exchange (buffer 1, phase (Tn>>1)&1 = 0):
    // exit safety + final h2 visible for the FC head
    mbar_wait_cl(smb + 16 + 8, 0);

    // FC head: final h2 = hb2 buffer 1 ([j][8] batch-major)
    if (rank == 0 && tid < 16) {
        int b = tid >> 1, cl = tid & 1;
        float s = fcb[cl];
        #pragma unroll
        for (int j = 0; j < 128; ++j)
            s = fmaf(hb2[1024 + j * 8 + b], fcW[cl * 128 + j], s);
        out[(b0 + b) * 2 + cl] = s;
    }
}

// ---------------------------------------------------------------------------
extern "C" void kernel_launch(void* const* d_in, const int* in_sizes, int n_in,
                              void* d_out, int out_size)
{
    const float* x    = (const float*)d_in[0];
    const float* Wih0 = (const float*)d_in[1];
    const float* Whh0 = (const float*)d_in[2];
    const float* bih0 = (const float*)d_in[3];
    const float* bhh0 = (const float*)d_in[4];
    const float* Wih1 = (const float*)d_in[5];
    const float* Whh1 = (const float*)d_in[6];
    const float* bih1 = (const float*)d_in[7];
    const float* bhh1 = (const float*)d_in[8];
    const float* fcW  = (const float*)d_in[9];
    const float* fcb  = (const float*)d_in[10];
    float* out = (float*)d_out;

    cudaFuncSetAttribute(lstm_fused, cudaFuncAttributeMaxDynamicSharedMemorySize,
                         SMEM_BYTES);
    lstm_fused<<<128, 512, SMEM_BYTES>>>(x, Wih0, Whh0, bih0, bhh0,
                                         Wih1, Whh1, bih1, bhh1, fcW, fcb, out);
}

// round 11
// speedup vs baseline: 1.3006x; 1.3006x over previous
#include <cuda_runtime.h>
#include <cstdint>

#define Tn 2048

// Layer-0 hidden states, layout [T][128 j][256 b] (batch-major innermost)
__device__ float g_h1[(size_t)Tn * 128 * 256];

__device__ __forceinline__ uint32_t smem_u32(const void* p) {
    return (uint32_t)__cvta_generic_to_shared(p);
}
__device__ __forceinline__ void cluster_sync_() {
    asm volatile("barrier.cluster.arrive.aligned;" ::: "memory");
    asm volatile("barrier.cluster.wait.aligned;" ::: "memory");
}
__device__ __forceinline__ uint32_t mapa_sh(uint32_t addr, uint32_t rank) {
    uint32_t r;
    asm("mapa.shared::cluster.u32 %0, %1, %2;" : "=r"(r) : "r"(addr), "r"(rank));
    return r;
}
__device__ __forceinline__ void mbar_init(uint32_t a, uint32_t cnt) {
    asm volatile("mbarrier.init.shared.b64 [%0], %1;" :: "r"(a), "r"(cnt) : "memory");
}
__device__ __forceinline__ void mbar_arm_tx(uint32_t a, uint32_t tx) {
    asm volatile("mbarrier.arrive.expect_tx.shared.b64 _, [%0], %1;"
                 :: "r"(a), "r"(tx) : "memory");
}
__device__ __forceinline__ void mbar_wait_cl(uint32_t a, uint32_t parity) {
    asm volatile(
        "{\n\t.reg .pred P;\n\t"
        "WL_%=:\n\t"
        "mbarrier.try_wait.parity.acquire.cluster.shared::cta.b64 P, [%0], %1, 0x989680;\n\t"
        "@P bra.uni WD_%=;\n\t"
        "bra.uni WL_%=;\n\t"
        "WD_%=:\n\t}"
        :: "r"(a), "r"(parity) : "memory");
}
__device__ __forceinline__ void bulk_dsmem(uint32_t dst, uint32_t src,
                                           uint32_t bytes, uint32_t mbar) {
    asm volatile(
        "cp.async.bulk.shared::cluster.shared::cta.mbarrier::complete_tx::bytes "
        "[%0], [%1], %2, [%3];"
        :: "r"(dst), "r"(src), "r"(bytes), "r"(mbar) : "memory");
}
__device__ __forceinline__ void fence_async_() {
    asm volatile("fence.proxy.async.shared::cta;" ::: "memory");
}
// named barriers: id 1 = "A" (gate partials ready), id 2 = "B" (combine done)
__device__ __forceinline__ void nbar_sync(int id) {
    asm volatile("bar.sync %0, 512;" :: "r"(id) : "memory");
}
__device__ __forceinline__ void nbar_arrive(int id) {
    asm volatile("bar.arrive %0, 512;" :: "r"(id) : "memory");
}
__device__ __forceinline__ float sigm(float v) { return 1.0f / (1.0f + __expf(-v)); }
__device__ __forceinline__ float tanh_(float v) { return 2.0f / (1.0f + __expf(-2.0f * v)) - 1.0f; }

__device__ __forceinline__ unsigned long long pk2(float v) {
    unsigned long long r;
    asm("mov.b64 %0, {%1, %1};" : "=l"(r) : "f"(v));
    return r;
}
__device__ __forceinline__ void ffma2(unsigned long long& d, unsigned long long a,
                                      unsigned long long b) {
    asm("fma.rn.f32x2 %0, %1, %2, %0;" : "+l"(d) : "l"(a), "l"(b));
}
__device__ __forceinline__ void unpk(unsigned long long v, float& lo, float& hi) {
    asm("mov.b64 {%0, %1}, %2;" : "=f"(lo), "=f"(hi) : "l"(v));
}
__device__ __forceinline__ float sel4(float4 v, int s) {
    return (s == 0) ? v.x : (s == 1) ? v.y : (s == 2) ? v.z : v.w;
}

// ---------------------------------------------------------------------------
// Layer 0 (r9 structure + producer/consumer split): cluster of 2 CTAs x 512
// threads, 4 batches/cluster. OWN group (tid<256, segs 0-1) computes the own
// hidden slice + x-projection, runs one step ahead gated by named-bar B.
// PEER group (tid>=256, segs 2-3) waits the DSMEM exchange, computes the peer
// slice, then does the combine + exchange. Exchange protocol identical to r9.
// smem floats: mbar[4] @0, hbuf [2][128][4] @4, xbuf [2][5][4] @1028,
//              gbuf [2][4][256][5] @1068 -> 11308 floats
// ---------------------------------------------------------------------------
#define SMEM0_BYTES (11308 * 4)

__global__ void __cluster_dims__(2, 1, 1) __launch_bounds__(512, 1)
lstm_layer0(const float* __restrict__ x, const float* __restrict__ Wih,
            const float* __restrict__ Whh, const float* __restrict__ bih,
            const float* __restrict__ bhh)
{
    extern __shared__ float sm[];
    const uint32_t smb = smem_u32(sm);
    float* hbuf = sm + 4;      // [2 par][128 j][4 b]
    float* xbuf = sm + 1028;   // [2 par][5 d][4 b]
    float* gbuf = sm + 1068;   // [2 par][4 seg][256 row][5]

    const int tid  = threadIdx.x;
    const int rank = blockIdx.x & 1;
    const int b0   = (blockIdx.x >> 1) * 4;

    const int seg = tid >> 7;                 // 0..3
    const int rp  = tid & 127;
    const int r0  = rp, r1 = rp + 128;
    const int kslice = (seg < 2) ? rank : (rank ^ 1);
    const int jbase  = kslice * 64 + (seg & 1) * 32;
    const int gr0 = ((r0 >> 6) << 7) + (rank << 6) + (r0 & 63);
    const int gr1 = ((r1 >> 6) << 7) + (rank << 6) + (r1 & 63);

    float4 wa[8], wb[8];
    {
        const float4* s0 = (const float4*)(Whh + gr0 * 128 + jbase);
        const float4* s1 = (const float4*)(Whh + gr1 * 128 + jbase);
        #pragma unroll
        for (int kk = 0; kk < 8; ++kk) { wa[kk] = s0[kk]; wb[kk] = s1[kk]; }
    }
    unsigned long long wx0[5], wx1[5], bb0 = 0ull, bb1 = 0ull;
    if (seg == 0) {
        bb0 = pk2(bih[gr0] + bhh[gr0]);
        bb1 = pk2(bih[gr1] + bhh[gr1]);
        #pragma unroll
        for (int d = 0; d < 5; ++d) {
            wx0[d] = pk2(Wih[gr0 * 5 + d]);
            wx1[d] = pk2(Wih[gr1 * 5 + d]);
        }
    }

    if (tid == 0) {
        mbar_init(smb + 0, 1);
        mbar_init(smb + 8, 1);
        mbar_arm_tx(smb + 0, 1024);
        mbar_arm_tx(smb + 8, 1024);
    }
    for (int i = tid; i < 1024; i += 512) hbuf[i] = 0.f;
    if (tid < 20) {
        int b = tid / 5, d = tid % 5;
        xbuf[d * 4 + b] = x[((size_t)(b0 + b) * Tn) * 5 + d];
    }
    const uint32_t peer = mapa_sh(smb, rank ^ 1);

    __syncthreads();
    cluster_sync_();
    if (tid == 0) {
        fence_async_();
        uint32_t off = (4 + rank * 256) * 4;
        bulk_dsmem(peer + off, smb + off, 1024, peer + 0);
    }

    if (tid < 256) {
        // ============ OWN group: own-slice + x, runs ahead under bar B ======
        for (int t = 0; t < Tn; ++t) {
            const int par = t & 1, nb = par ^ 1;
            float pre = 0.f;
            if (tid < 20 && t + 1 < Tn) {
                int b = tid / 5, d = tid % 5;
                pre = x[((size_t)(b0 + b) * Tn + (t + 1)) * 5 + d];
            }
            if (t) nbar_sync(2);   // combine(t-1) done: h_self(t-1)+gbuf free
            unsigned long long a0lo = bb0, a0hi = bb0, a1lo = bb1, a1hi = bb1;
            if (seg == 0) {
                const float* xb = xbuf + par * 20;
                #pragma unroll
                for (int d = 0; d < 5; ++d) {
                    unsigned long long xlo = *(const unsigned long long*)(xb + d * 4);
                    unsigned long long xhi = *(const unsigned long long*)(xb + d * 4 + 2);
                    ffma2(a0lo, wx0[d], xlo); ffma2(a0hi, wx0[d], xhi);
                    ffma2(a1lo, wx1[d], xlo); ffma2(a1hi, wx1[d], xhi);
                }
            }
            const float* hp = hbuf + par * 512 + jbase * 4;
            #pragma unroll
            for (int kk = 0; kk < 8; ++kk) {
                float4 w0v = wa[kk], w1v = wb[kk];
                #pragma unroll
                for (int s = 0; s < 4; ++s) {
                    ulonglong2 hv = *(const ulonglong2*)(hp + (kk * 4 + s) * 4);
                    unsigned long long p0 = pk2(sel4(w0v, s));
                    ffma2(a0lo, p0, hv.x); ffma2(a0hi, p0, hv.y);
                    unsigned long long p1 = pk2(sel4(w1v, s));
                    ffma2(a1lo, p1, hv.x); ffma2(a1hi, p1, hv.y);
                }
            }
            {
                float* gp = gbuf + par * 5120 + seg * 1280;
                float v0, v1;
                unpk(a0lo, v0, v1); gp[r0 * 5 + 0] = v0; gp[r0 * 5 + 1] = v1;
                unpk(a0hi, v0, v1); gp[r0 * 5 + 2] = v0; gp[r0 * 5 + 3] = v1;
                unpk(a1lo, v0, v1); gp[r1 * 5 + 0] = v0; gp[r1 * 5 + 1] = v1;
                unpk(a1hi, v0, v1); gp[r1 * 5 + 2] = v0; gp[r1 * 5 + 3] = v1;
            }
            nbar_arrive(1);        // partials(t) ready for PEER's combine
            if (tid < 20 && t + 1 < Tn) {
                int b = tid / 5, d = tid % 5;
                xbuf[nb * 20 + d * 4 + b] = pre;
            }
        }
    } else {
        // ============ PEER group: wait -> peer slice -> combine -> ship =====
        float c = 0.f;
        const int ct = tid - 256;
        const int cb = ct & 3, cj = (ct >> 2) & 63;
        for (int t = 0; t < Tn; ++t) {
            const int par = t & 1, nb = par ^ 1;
            {
                uint32_t mb = smb + par * 8;
                mbar_wait_cl(mb, (t >> 1) & 1);
                if (tid == 256) mbar_arm_tx(mb, 1024);
            }
            unsigned long long a0lo = 0ull, a0hi = 0ull, a1lo = 0ull, a1hi = 0ull;
            const float* hp = hbuf + par * 512 + jbase * 4;
            #pragma unroll
            for (int kk = 0; kk < 8; ++kk) {
                float4 w0v = wa[kk], w1v = wb[kk];
                #pragma unroll
                for (int s = 0; s < 4; ++s) {
                    ulonglong2 hv = *(const ulonglong2*)(hp + (kk * 4 + s) * 4);
                    unsigned long long p0 = pk2(sel4(w0v, s));
                    ffma2(a0lo, p0, hv.x); ffma2(a0hi, p0, hv.y);
                    unsigned long long p1 = pk2(sel4(w1v, s));
                    ffma2(a1lo, p1, hv.x); ffma2(a1hi, p1, hv.y);
                }
            }
            {
                float* gp = gbuf + par * 5120 + seg * 1280;
                float v0, v1;
                unpk(a0lo, v0, v1); gp[r0 * 5 + 0] = v0; gp[r0 * 5 + 1] = v1;
                unpk(a0hi, v0, v1); gp[r0 * 5 + 2] = v0; gp[r0 * 5 + 3] = v1;
                unpk(a1lo, v0, v1); gp[r1 * 5 + 0] = v0; gp[r1 * 5 + 1] = v1;
                unpk(a1hi, v0, v1); gp[r1 * 5 + 2] = v0; gp[r1 * 5 + 3] = v1;
            }
            nbar_sync(1);          // wait OWN partials(t)
            {
                const float* gq = gbuf + par * 5120;
                float gv[4];
                #pragma unroll
                for (int g = 0; g < 4; ++g) {
                    int r = g * 64 + cj;
                    gv[g] = gq[r * 5 + cb] + gq[1280 + r * 5 + cb]
                          + gq[2560 + r * 5 + cb] + gq[3840 + r * 5 + cb];
                }
                float ii = sigm(gv[0]), ff = sigm(gv[1]), g = tanh_(gv[2]), oo = sigm(gv[3]);
                c = fmaf(ff, c, ii * g);
                float h = oo * tanh_(c);
                hbuf[nb * 512 + rank * 256 + ct] = h;   // self slice (STS)
                g_h1[((size_t)t * 128 + (rank << 6) + cj) * 256 + b0 + cb] = h;
                nbar_arrive(2);    // combine(t) done: release OWN for t+1
                __syncwarp();
                if ((ct & 31) == 0) {
                    fence_async_();
                    uint32_t off = (4 + nb * 512 + rank * 256 + (ct & 224)) * 4;
                    bulk_dsmem(peer + off, smb + off, 128, peer + nb * 8);
                }
            }
        }
    }
    // consume the final exchange (exit safety)
    mbar_wait_cl(smb + 0, 0);
}

// ---------------------------------------------------------------------------
// Layer 1 + FC (r9 structure + producer/consumer split): cluster of 4 CTAs x
// 512 threads, 8 batches/cluster. IH group (tid<256, segs 0-3) computes W_ih
// over gmem-prefetched h1(t) and runs one step ahead under bar B; HH group
// (tid>=256, segs 4-7) waits the h2 exchange, computes W_hh, combines, ships.
// Exchange protocol identical to r9.
// smem floats: mbar[4] @0, hbuf [2][128][8] @4, sbuf [2][128][8] @2052,
//              stage [2][256] @4100, gbuf [2][8][128][9] @4612 -> 23044 floats
// ---------------------------------------------------------------------------
#define SMEM1_BYTES (23044 * 4)

__global__ void __cluster_dims__(4, 1, 1) __launch_bounds__(512, 1)
lstm_layer1(const float* __restrict__ Wih, const float* __restrict__ Whh,
            const float* __restrict__ bih, const float* __restrict__ bhh,
            const float* __restrict__ fcW, const float* __restrict__ fcb,
            float* __restrict__ out)
{
    extern __shared__ float sm[];
    const uint32_t smb = smem_u32(sm);
    float* hbuf  = sm + 4;     // [2 par][128 j][8 b]
    float* sbuf  = sm + 2052;  // [2 par][128 j][8 b]
    float* stage = sm + 4100;  // [2 par][256]
    float* gbuf  = sm + 4612;  // [2 par][8 seg][128 row][9]

    const int tid  = threadIdx.x;
    const int rank = blockIdx.x & 3;
    const int b0   = (blockIdx.x >> 2) * 8;

    const int seg = tid >> 6;                 // 0..7
    const int rp  = tid & 63;
    const int r0  = rp, r1 = rp + 64;
    const int gr0 = ((r0 >> 5) << 7) + (rank << 5) + (r0 & 31);
    const int gr1 = ((r1 >> 5) << 7) + (rank << 5) + (r1 & 31);

    float4 wa[8], wb[8];
    {
        const float* wm = (seg < 4) ? Wih : Whh;
        const float4* s0 = (const float4*)(wm + gr0 * 128 + (seg & 3) * 32);
        const float4* s1 = (const float4*)(wm + gr1 * 128 + (seg & 3) * 32);
        #pragma unroll
        for (int kk = 0; kk < 8; ++kk) { wa[kk] = s0[kk]; wb[kk] = s1[kk]; }
    }
    unsigned long long bb0 = 0ull, bb1 = 0ull;
    if (seg == 0) {
        bb0 = pk2(bih[gr0] + bhh[gr0]);
        bb1 = pk2(bih[gr1] + bhh[gr1]);
    }

    if (tid == 0) {
        mbar_init(smb + 0, 1);
        mbar_init(smb + 8, 1);
        mbar_arm_tx(smb + 0, 4096);
        mbar_arm_tx(smb + 8, 4096);
    }
    for (int i = tid; i < 2048; i += 512) hbuf[i]  = 0.f;
    if (tid < 512) stage[tid & 511] = 0.f;

    // initial h1(0) staging: all 512 float2 slots (each thread covers 1)
    {
        int sj = tid >> 2, pq = tid & 3;
        float2 v = *(const float2*)(g_h1 + (size_t)sj * 256 + b0 + pq * 2);
        *(float2*)(sbuf + sj * 8 + pq * 2) = v;
    }
    uint32_t base[4];
    #pragma unroll
    for (int r = 0; r < 4; ++r) base[r] = mapa_sh(smb, r);

    __syncthreads();
    cluster_sync_();
    if (tid < 4) {   // prime h2(-1)=0 exchange into slot 0 / mbar 0
        fence_async_();
        bulk_dsmem(base[tid] + (4 + rank * 256) * 4, smb + 4100 * 4,
                   1024, base[tid] + 0);
    }

    if (tid < 256) {
        // ============ IH group: W_ih over prefetched h1, runs ahead =========
        const int sj0 = tid >> 2, pq0 = tid & 3;        // covers idx tid
        const int sj1 = sj0 + 64;                       // covers idx tid+256
        for (int t = 0; t < Tn; ++t) {
            const int par = t & 1, nb = par ^ 1;
            float2 preA = make_float2(0.f, 0.f), preB = make_float2(0.f, 0.f);
            if (t + 1 < Tn) {
                preA = *(const float2*)(g_h1 + ((size_t)(t + 1) * 128 + sj0) * 256 + b0 + pq0 * 2);
                preB = *(const float2*)(g_h1 + ((size_t)(t + 1) * 128 + sj1) * 256 + b0 + pq0 * 2);
            }
            if (t) nbar_sync(2);   // combine(t-1) done: gbuf[par] free
            unsigned long long a0[4], a1[4];
            #pragma unroll
            for (int i = 0; i < 4; ++i) { a0[i] = bb0; a1[i] = bb1; }
            const float* src = sbuf + par * 1024 + (seg & 3) * 256;
            #pragma unroll
            for (int kk = 0; kk < 8; ++kk) {
                float4 w0v = wa[kk], w1v = wb[kk];
                #pragma unroll
                for (int s = 0; s < 4; ++s) {
                    const float* p = src + (kk * 4 + s) * 8;
                    ulonglong2 h0 = *(const ulonglong2*)(p);
                    ulonglong2 h1v = *(const ulonglong2*)(p + 4);
                    unsigned long long p0 = pk2(sel4(w0v, s));
                    ffma2(a0[0], p0, h0.x); ffma2(a0[1], p0, h0.y);
                    ffma2(a0[2], p0, h1v.x); ffma2(a0[3], p0, h1v.y);
                    unsigned long long p1 = pk2(sel4(w1v, s));
                    ffma2(a1[0], p1, h0.x); ffma2(a1[1], p1, h0.y);
                    ffma2(a1[2], p1, h1v.x); ffma2(a1[3], p1, h1v.y);
                }
            }
            {
                float* gp = gbuf + (par * 8 + seg) * 1152;
                float v0, v1;
                #pragma unroll
                for (int i = 0; i < 4; ++i) {
                    unpk(a0[i], v0, v1);
                    gp[r0 * 9 + i * 2] = v0; gp[r0 * 9 + i * 2 + 1] = v1;
                }
                #pragma unroll
                for (int i = 0; i < 4; ++i) {
                    unpk(a1[i], v0, v1);
                    gp[r1 * 9 + i * 2] = v0; gp[r1 * 9 + i * 2 + 1] = v1;
                }
            }
            nbar_arrive(1);        // partials(t) ready
            if (t + 1 < Tn) {
                *(float2*)(sbuf + nb * 1024 + sj0 * 8 + pq0 * 2) = preA;
                *(float2*)(sbuf + nb * 1024 + sj1 * 8 + pq0 * 2) = preB;
            }
        }
    } else {
        // ============ HH group: wait -> W_hh -> combine -> ship =============
        float c = 0.f;
        const int ct = tid - 256;
        const int cb = ct & 7, cj = (ct >> 3) & 31;
        for (int t = 0; t < Tn; ++t) {
            const int par = t & 1, nb = par ^ 1;
            {
                uint32_t mb = smb + par * 8;
                mbar_wait_cl(mb, (t >> 1) & 1);
                if (tid == 256) mbar_arm_tx(mb, 4096);
            }
            unsigned long long a0[4], a1[4];
            #pragma unroll
            for (int i = 0; i < 4; ++i) { a0[i] = 0ull; a1[i] = 0ull; }
            const float* src = hbuf + par * 1024 + (seg & 3) * 256;
            #pragma unroll
            for (int kk = 0; kk < 8; ++kk) {
                float4 w0v = wa[kk], w1v = wb[kk];
                #pragma unroll
                for (int s = 0; s < 4; ++s) {
                    const float* p = src + (kk * 4 + s) * 8;
                    ulonglong2 h0 = *(const ulonglong2*)(p);
                    ulonglong2 h1v = *(const ulonglong2*)(p + 4);
                    unsigned long long p0 = pk2(sel4(w0v, s));
                    ffma2(a0[0], p0, h0.x); ffma2(a0[1], p0, h0.y);
                    ffma2(a0[2], p0, h1v.x); ffma2(a0[3], p0, h1v.y);
                    unsigned long long p1 = pk2(sel4(w1v, s));
                    ffma2(a1[0], p1, h0.x); ffma2(a1[1], p1, h0.y);
                    ffma2(a1[2], p1, h1v.x); ffma2(a1[3], p1, h1v.y);
                }
            }
            {
                float* gp = gbuf + (par * 8 + seg) * 1152;
                float v0, v1;
                #pragma unroll
                for (int i = 0; i < 4; ++i) {
                    unpk(a0[i], v0, v1);
                    gp[r0 * 9 + i * 2] = v0; gp[r0 * 9 + i * 2 + 1] = v1;
                }
                #pragma unroll
                for (int i = 0; i < 4; ++i) {
                    unpk(a1[i], v0, v1);
                    gp[r1 * 9 + i * 2] = v0; gp[r1 * 9 + i * 2 + 1] = v1;
                }
            }
            nbar_sync(1);          // wait IH partials(t)
            {
                const float* gq = gbuf + par * 9216;
                float gv[4];
                #pragma unroll
                for (int g = 0; g < 4; ++g) {
                    int r = g * 32 + cj;
                    float s = 0.f;
                    #pragma unroll
                    for (int sg = 0; sg < 8; ++sg) s += gq[sg * 1152 + r * 9 + cb];
                    gv[g] = s;
                }
                float ii = sigm(gv[0]), ff = sigm(gv[1]), g = tanh_(gv[2]), oo = sigm(gv[3]);
                c = fmaf(ff, c, ii * g);
                float h = oo * tanh_(c);
                stage[nb * 256 + ct] = h;
                nbar_arrive(2);    // combine(t) done: release IH for t+1
                __syncwarp();
                if ((ct & 31) < 4) {
                    int dr = ct & 31;
                    fence_async_();
                    uint32_t dsto = (4 + nb * 1024 + rank * 256 + (ct & 224)) * 4;
                    uint32_t srco = (4100 + nb * 256 + (ct & 224)) * 4;
                    bulk_dsmem(base[dr] + dsto, smb + srco, 128, base[dr] + nb * 8);
                }
            }
        }
    }
    // consume the final exchange (slot 0) — exit safety + final h2 visible
    mbar_wait_cl(smb + 0, 0);

    // FC head: final h2 in hbuf slot 0 ([j][8] batch-major)
    if (rank == 0 && tid < 16) {
        int b = tid >> 1, cl = tid & 1;
        float s = fcb[cl];
        #pragma unroll
        for (int j = 0; j < 128; ++j) s = fmaf(hbuf[j * 8 + b], fcW[cl * 128 + j], s);
        out[(b0 + b) * 2 + cl] = s;
    }
}

// ---------------------------------------------------------------------------
extern "C" void kernel_launch(void* const* d_in, const int* in_sizes, int n_in,
                              void* d_out, int out_size)
{
    const float* x    = (const float*)d_in[0];
    const float* Wih0 = (const float*)d_in[1];
    const float* Whh0 = (const float*)d_in[2];
    const float* bih0 = (const float*)d_in[3];
    const float* bhh0 = (const float*)d_in[4];
    const float* Wih1 = (const float*)d_in[5];
    const float* Whh1 = (const float*)d_in[6];
    const float* bih1 = (const float*)d_in[7];
    const float* bhh1 = (const float*)d_in[8];
    const float* fcW  = (const float*)d_in[9];
    const float* fcb  = (const float*)d_in[10];
    float* out = (float*)d_out;

    cudaFuncSetAttribute(lstm_layer0, cudaFuncAttributeMaxDynamicSharedMemorySize, SMEM0_BYTES);
    cudaFuncSetAttribute(lstm_layer1, cudaFuncAttributeMaxDynamicSharedMemorySize, SMEM1_BYTES);

    lstm_layer0<<<128, 512, SMEM0_BYTES>>>(x, Wih0, Whh0, bih0, bhh0);
    lstm_layer1<<<128, 512, SMEM1_BYTES>>>(Wih1, Whh1, bih1, bhh1, fcW, fcb, out);
}

// round 12
// speedup vs baseline: 1.3007x; 1.0001x over previous
#include <cuda_runtime.h>
#include <cstdint>

#define Tn 2048

// Layer-0 hidden states, layout [T][128 j][256 b] (batch-major innermost)
__device__ float g_h1[(size_t)Tn * 128 * 256];

__device__ __forceinline__ uint32_t smem_u32(const void* p) {
    return (uint32_t)__cvta_generic_to_shared(p);
}
__device__ __forceinline__ void cluster_sync_() {
    asm volatile("barrier.cluster.arrive.aligned;" ::: "memory");
    asm volatile("barrier.cluster.wait.aligned;" ::: "memory");
}
__device__ __forceinline__ uint32_t mapa_sh(uint32_t addr, uint32_t rank) {
    uint32_t r;
    asm("mapa.shared::cluster.u32 %0, %1, %2;" : "=r"(r) : "r"(addr), "r"(rank));
    return r;
}
__device__ __forceinline__ void mbar_init(uint32_t a, uint32_t cnt) {
    asm volatile("mbarrier.init.shared.b64 [%0], %1;" :: "r"(a), "r"(cnt) : "memory");
}
__device__ __forceinline__ void mbar_arm_tx(uint32_t a, uint32_t tx) {
    asm volatile("mbarrier.arrive.expect_tx.shared.b64 _, [%0], %1;"
                 :: "r"(a), "r"(tx) : "memory");
}
__device__ __forceinline__ void mbar_wait_cl(uint32_t a, uint32_t parity) {
    asm volatile(
        "{\n\t.reg .pred P;\n\t"
        "WL_%=:\n\t"
        "mbarrier.try_wait.parity.acquire.cluster.shared::cta.b64 P, [%0], %1, 0x989680;\n\t"
        "@P bra.uni WD_%=;\n\t"
        "bra.uni WL_%=;\n\t"
        "WD_%=:\n\t}"
        :: "r"(a), "r"(parity) : "memory");
}
__device__ __forceinline__ void bulk_dsmem(uint32_t dst, uint32_t src,
                                           uint32_t bytes, uint32_t mbar) {
    asm volatile(
        "cp.async.bulk.shared::cluster.shared::cta.mbarrier::complete_tx::bytes "
        "[%0], [%1], %2, [%3];"
        :: "r"(dst), "r"(src), "r"(bytes), "r"(mbar) : "memory");
}
__device__ __forceinline__ void fence_async_() {
    asm volatile("fence.proxy.async.shared::cta;" ::: "memory");
}
// named barriers: id 1 = "A" (gate partials ready), id 2 = "B" (combine done)
__device__ __forceinline__ void nbar_sync(int id) {
    asm volatile("bar.sync %0, 512;" :: "r"(id) : "memory");
}
__device__ __forceinline__ void nbar_arrive(int id) {
    asm volatile("bar.arrive %0, 512;" :: "r"(id) : "memory");
}
__device__ __forceinline__ float sigm(float v) { return 1.0f / (1.0f + __expf(-v)); }
__device__ __forceinline__ float tanh_(float v) { return 2.0f / (1.0f + __expf(-2.0f * v)) - 1.0f; }

__device__ __forceinline__ unsigned long long pk2(float v) {
    unsigned long long r;
    asm("mov.b64 %0, {%1, %1};" : "=l"(r) : "f"(v));
    return r;
}
__device__ __forceinline__ void ffma2(unsigned long long& d, unsigned long long a,
                                      unsigned long long b) {
    asm("fma.rn.f32x2 %0, %1, %2, %0;" : "+l"(d) : "l"(a), "l"(b));
}
__device__ __forceinline__ void unpk(unsigned long long v, float& lo, float& hi) {
    asm("mov.b64 {%0, %1}, %2;" : "=f"(lo), "=f"(hi) : "l"(v));
}
__device__ __forceinline__ float sel4(float4 v, int s) {
    return (s == 0) ? v.x : (s == 1) ? v.y : (s == 2) ? v.z : v.w;
}

// ---------------------------------------------------------------------------
// Layer 0 (r9 structure + producer/consumer split): cluster of 2 CTAs x 512
// threads, 4 batches/cluster. OWN group (tid<256, segs 0-1) computes the own
// hidden slice + x-projection, runs one step ahead gated by named-bar B.
// PEER group (tid>=256, segs 2-3) waits the DSMEM exchange, computes the peer
// slice, then does the combine + exchange. Exchange protocol identical to r9.
// smem floats: mbar[4] @0, hbuf [2][128][4] @4, xbuf [2][5][4] @1028,
//              gbuf [2][4][256][5] @1068 -> 11308 floats
// ---------------------------------------------------------------------------
#define SMEM0_BYTES (11308 * 4)

__global__ void __cluster_dims__(2, 1, 1) __launch_bounds__(512, 1)
lstm_layer0(const float* __restrict__ x, const float* __restrict__ Wih,
            const float* __restrict__ Whh, const float* __restrict__ bih,
            const float* __restrict__ bhh)
{
    extern __shared__ float sm[];
    const uint32_t smb = smem_u32(sm);
    float* hbuf = sm + 4;      // [2 par][128 j][4 b]
    float* xbuf = sm + 1028;   // [2 par][5 d][4 b]
    float* gbuf = sm + 1068;   // [2 par][4 seg][256 row][5]

    const int tid  = threadIdx.x;
    const int rank = blockIdx.x & 1;
    const int b0   = (blockIdx.x >> 1) * 4;

    const int seg = tid >> 7;                 // 0..3
    const int rp  = tid & 127;
    const int r0  = rp, r1 = rp + 128;
    const int kslice = (seg < 2) ? rank : (rank ^ 1);
    const int jbase  = kslice * 64 + (seg & 1) * 32;
    const int gr0 = ((r0 >> 6) << 7) + (rank << 6) + (r0 & 63);
    const int gr1 = ((r1 >> 6) << 7) + (rank << 6) + (r1 & 63);

    float4 wa[8], wb[8];
    {
        const float4* s0 = (const float4*)(Whh + gr0 * 128 + jbase);
        const float4* s1 = (const float4*)(Whh + gr1 * 128 + jbase);
        #pragma unroll
        for (int kk = 0; kk < 8; ++kk) { wa[kk] = s0[kk]; wb[kk] = s1[kk]; }
    }
    unsigned long long wx0[5], wx1[5], bb0 = 0ull, bb1 = 0ull;
    if (seg == 0) {
        bb0 = pk2(bih[gr0] + bhh[gr0]);
        bb1 = pk2(bih[gr1] + bhh[gr1]);
        #pragma unroll
        for (int d = 0; d < 5; ++d) {
            wx0[d] = pk2(Wih[gr0 * 5 + d]);
            wx1[d] = pk2(Wih[gr1 * 5 + d]);
        }
    }

    if (tid == 0) {
        mbar_init(smb + 0, 1);
        mbar_init(smb + 8, 1);
        mbar_arm_tx(smb + 0, 1024);
        mbar_arm_tx(smb + 8, 1024);
    }
    for (int i = tid; i < 1024; i += 512) hbuf[i] = 0.f;
    if (tid < 20) {
        int b = tid / 5, d = tid % 5;
        xbuf[d * 4 + b] = x[((size_t)(b0 + b) * Tn) * 5 + d];
    }
    const uint32_t peer = mapa_sh(smb, rank ^ 1);

    __syncthreads();
    cluster_sync_();
    if (tid == 0) {
        fence_async_();
        uint32_t off = (4 + rank * 256) * 4;
        bulk_dsmem(peer + off, smb + off, 1024, peer + 0);
    }

    if (tid < 256) {
        // ============ OWN group: own-slice + x, runs ahead under bar B ======
        for (int t = 0; t < Tn; ++t) {
            const int par = t & 1, nb = par ^ 1;
            float pre = 0.f;
            if (tid < 20 && t + 1 < Tn) {
                int b = tid / 5, d = tid % 5;
                pre = x[((size_t)(b0 + b) * Tn + (t + 1)) * 5 + d];
            }
            if (t) nbar_sync(2);   // combine(t-1) done: h_self(t-1)+gbuf free
            unsigned long long a0lo = bb0, a0hi = bb0, a1lo = bb1, a1hi = bb1;
            if (seg == 0) {
                const float* xb = xbuf + par * 20;
                #pragma unroll
                for (int d = 0; d < 5; ++d) {
                    unsigned long long xlo = *(const unsigned long long*)(xb + d * 4);
                    unsigned long long xhi = *(const unsigned long long*)(xb + d * 4 + 2);
                    ffma2(a0lo, wx0[d], xlo); ffma2(a0hi, wx0[d], xhi);
                    ffma2(a1lo, wx1[d], xlo); ffma2(a1hi, wx1[d], xhi);
                }
            }
            const float* hp = hbuf + par * 512 + jbase * 4;
            #pragma unroll
            for (int kk = 0; kk < 8; ++kk) {
                float4 w0v = wa[kk], w1v = wb[kk];
                #pragma unroll
                for (int s = 0; s < 4; ++s) {
                    ulonglong2 hv = *(const ulonglong2*)(hp + (kk * 4 + s) * 4);
                    unsigned long long p0 = pk2(sel4(w0v, s));
                    ffma2(a0lo, p0, hv.x); ffma2(a0hi, p0, hv.y);
                    unsigned long long p1 = pk2(sel4(w1v, s));
                    ffma2(a1lo, p1, hv.x); ffma2(a1hi, p1, hv.y);
                }
            }
            {
                float* gp = gbuf + par * 5120 + seg * 1280;
                float v0, v1;
                unpk(a0lo, v0, v1); gp[r0 * 5 + 0] = v0; gp[r0 * 5 + 1] = v1;
                unpk(a0hi, v0, v1); gp[r0 * 5 + 2] = v0; gp[r0 * 5 + 3] = v1;
                unpk(a1lo, v0, v1); gp[r1 * 5 + 0] = v0; gp[r1 * 5 + 1] = v1;
                unpk(a1hi, v0, v1); gp[r1 * 5 + 2] = v0; gp[r1 * 5 + 3] = v1;
            }
            nbar_arrive(1);        // partials(t) ready for PEER's combine
            if (tid < 20 && t + 1 < Tn) {
                int b = tid / 5, d = tid % 5;
                xbuf[nb * 20 + d * 4 + b] = pre;
            }
        }
    } else {
        // ============ PEER group: wait -> peer slice -> combine -> ship =====
        float c = 0.f;
        const int ct = tid - 256;
        const int cb = ct & 3, cj = (ct >> 2) & 63;
        for (int t = 0; t < Tn; ++t) {
            const int par = t & 1, nb = par ^ 1;
            {
                uint32_t mb = smb + par * 8;
                mbar_wait_cl(mb, (t >> 1) & 1);
                if (tid == 256) mbar_arm_tx(mb, 1024);
            }
            unsigned long long a0lo = 0ull, a0hi = 0ull, a1lo = 0ull, a1hi = 0ull;
            const float* hp = hbuf + par * 512 + jbase * 4;
            #pragma unroll
            for (int kk = 0; kk < 8; ++kk) {
                float4 w0v = wa[kk], w1v = wb[kk];
                #pragma unroll
                for (int s = 0; s < 4; ++s) {
                    ulonglong2 hv = *(const ulonglong2*)(hp + (kk * 4 + s) * 4);
                    unsigned long long p0 = pk2(sel4(w0v, s));
                    ffma2(a0lo, p0, hv.x); ffma2(a0hi, p0, hv.y);
                    unsigned long long p1 = pk2(sel4(w1v, s));
                    ffma2(a1lo, p1, hv.x); ffma2(a1hi, p1, hv.y);
                }
            }
            {
                float* gp = gbuf + par * 5120 + seg * 1280;
                float v0, v1;
                unpk(a0lo, v0, v1); gp[r0 * 5 + 0] = v0; gp[r0 * 5 + 1] = v1;
                unpk(a0hi, v0, v1); gp[r0 * 5 + 2] = v0; gp[r0 * 5 + 3] = v1;
                unpk(a1lo, v0, v1); gp[r1 * 5 + 0] = v0; gp[r1 * 5 + 1] = v1;
                unpk(a1hi, v0, v1); gp[r1 * 5 + 2] = v0; gp[r1 * 5 + 3] = v1;
            }
            nbar_sync(1);          // wait OWN partials(t)
            {
                const float* gq = gbuf + par * 5120;
                float gv[4];
                #pragma unroll
                for (int g = 0; g < 4; ++g) {
                    int r = g * 64 + cj;
                    gv[g] = gq[r * 5 + cb] + gq[1280 + r * 5 + cb]
                          + gq[2560 + r * 5 + cb] + gq[3840 + r * 5 + cb];
                }
                float ii = sigm(gv[0]), ff = sigm(gv[1]), g = tanh_(gv[2]), oo = sigm(gv[3]);
                c = fmaf(ff, c, ii * g);
                float h = oo * tanh_(c);
                hbuf[nb * 512 + rank * 256 + ct] = h;   // self slice (STS)
                g_h1[((size_t)t * 128 + (rank << 6) + cj) * 256 + b0 + cb] = h;
                nbar_arrive(2);    // combine(t) done: release OWN for t+1
                __syncwarp();
                if ((ct & 31) == 0) {
                    fence_async_();
                    uint32_t off = (4 + nb * 512 + rank * 256 + (ct & 224)) * 4;
                    bulk_dsmem(peer + off, smb + off, 128, peer + nb * 8);
                }
            }
        }
    }
    // consume the final exchange (exit safety)
    mbar_wait_cl(smb + 0, 0);
}

// ---------------------------------------------------------------------------
// Layer 1 + FC (r9 structure + producer/consumer split): cluster of 4 CTAs x
// 512 threads, 8 batches/cluster. IH group (tid<256, segs 0-3) computes W_ih
// over gmem-prefetched h1(t) and runs one step ahead under bar B; HH group
// (tid>=256, segs 4-7) waits the h2 exchange, computes W_hh, combines, ships.
// Exchange protocol identical to r9.
// smem floats: mbar[4] @0, hbuf [2][128][8] @4, sbuf [2][128][8] @2052,
//              stage [2][256] @4100, gbuf [2][8][128][9] @4612 -> 23044 floats
// ---------------------------------------------------------------------------
#define SMEM1_BYTES (23044 * 4)

__global__ void __cluster_dims__(4, 1, 1) __launch_bounds__(512, 1)
lstm_layer1(const float* __restrict__ Wih, const float* __restrict__ Whh,
            const float* __restrict__ bih, const float* __restrict__ bhh,
            const float* __restrict__ fcW, const float* __restrict__ fcb,
            float* __restrict__ out)
{
    extern __shared__ float sm[];
    const uint32_t smb = smem_u32(sm);
    float* hbuf  = sm + 4;     // [2 par][128 j][8 b]
    float* sbuf  = sm + 2052;  // [2 par][128 j][8 b]
    float* stage = sm + 4100;  // [2 par][256]
    float* gbuf  = sm + 4612;  // [2 par][8 seg][128 row][9]

    const int tid  = threadIdx.x;
    const int rank = blockIdx.x & 3;
    const int b0   = (blockIdx.x >> 2) * 8;

    const int seg = tid >> 6;                 // 0..7
    const int rp  = tid & 63;
    const int r0  = rp, r1 = rp + 64;
    const int gr0 = ((r0 >> 5) << 7) + (rank << 5) + (r0 & 31);
    const int gr1 = ((r1 >> 5) << 7) + (rank << 5) + (r1 & 31);

    float4 wa[8], wb[8];
    {
        const float* wm = (seg < 4) ? Wih : Whh;
        const float4* s0 = (const float4*)(wm + gr0 * 128 + (seg & 3) * 32);
        const float4* s1 = (const float4*)(wm + gr1 * 128 + (seg & 3) * 32);
        #pragma unroll
        for (int kk = 0; kk < 8; ++kk) { wa[kk] = s0[kk]; wb[kk] = s1[kk]; }
    }
    unsigned long long bb0 = 0ull, bb1 = 0ull;
    if (seg == 0) {
        bb0 = pk2(bih[gr0] + bhh[gr0]);
        bb1 = pk2(bih[gr1] + bhh[gr1]);
    }

    if (tid == 0) {
        mbar_init(smb + 0, 1);
        mbar_init(smb + 8, 1);
        mbar_arm_tx(smb + 0, 4096);
        mbar_arm_tx(smb + 8, 4096);
    }
    for (int i = tid; i < 2048; i += 512) hbuf[i]  = 0.f;
    if (tid < 512) stage[tid & 511] = 0.f;

    // initial h1(0) staging: all 512 float2 slots (each thread covers 1)
    {
        int sj = tid >> 2, pq = tid & 3;
        float2 v = *(const float2*)(g_h1 + (size_t)sj * 256 + b0 + pq * 2);
        *(float2*)(sbuf + sj * 8 + pq * 2) = v;
    }
    uint32_t base[4];
    #pragma unroll
    for (int r = 0; r < 4; ++r) base[r] = mapa_sh(smb, r);

    __syncthreads();
    cluster_sync_();
    if (tid < 4) {   // prime h2(-1)=0 exchange into slot 0 / mbar 0
        fence_async_();
        bulk_dsmem(base[tid] + (4 + rank * 256) * 4, smb + 4100 * 4,
                   1024, base[tid] + 0);
    }

    if (tid < 256) {
        // ============ IH group: W_ih over prefetched h1, runs ahead =========
        const int sj0 = tid >> 2, pq0 = tid & 3;        // covers idx tid
        const int sj1 = sj0 + 64;                       // covers idx tid+256
        for (int t = 0; t < Tn; ++t) {
            const int par = t & 1, nb = par ^ 1;
            float2 preA = make_float2(0.f, 0.f), preB = make_float2(0.f, 0.f);
            if (t + 1 < Tn) {
                preA = *(const float2*)(g_h1 + ((size_t)(t + 1) * 128 + sj0) * 256 + b0 + pq0 * 2);
                preB = *(const float2*)(g_h1 + ((size_t)(t + 1) * 128 + sj1) * 256 + b0 + pq0 * 2);
            }
            if (t) nbar_sync(2);   // combine(t-1) done: gbuf[par] free
            unsigned long long a0[4], a1[4];
            #pragma unroll
            for (int i = 0; i < 4; ++i) { a0[i] = bb0; a1[i] = bb1; }
            const float* src = sbuf + par * 1024 + (seg & 3) * 256;
            #pragma unroll
            for (int kk = 0; kk < 8; ++kk) {
                float4 w0v = wa[kk], w1v = wb[kk];
                #pragma unroll
                for (int s = 0; s < 4; ++s) {
                    const float* p = src + (kk * 4 + s) * 8;
                    ulonglong2 h0 = *(const ulonglong2*)(p);
                    ulonglong2 h1v = *(const ulonglong2*)(p + 4);
                    unsigned long long p0 = pk2(sel4(w0v, s));
                    ffma2(a0[0], p0, h0.x); ffma2(a0[1], p0, h0.y);
                    ffma2(a0[2], p0, h1v.x); ffma2(a0[3], p0, h1v.y);
                    unsigned long long p1 = pk2(sel4(w1v, s));
                    ffma2(a1[0], p1, h0.x); ffma2(a1[1], p1, h0.y);
                    ffma2(a1[2], p1, h1v.x); ffma2(a1[3], p1, h1v.y);
                }
            }
            {
                float* gp = gbuf + (par * 8 + seg) * 1152;
                float v0, v1;
                #pragma unroll
                for (int i = 0; i < 4; ++i) {
                    unpk(a0[i], v0, v1);
                    gp[r0 * 9 + i * 2] = v0; gp[r0 * 9 + i * 2 + 1] = v1;
                }
                #pragma unroll
                for (int i = 0; i < 4; ++i) {
                    unpk(a1[i], v0, v1);
                    gp[r1 * 9 + i * 2] = v0; gp[r1 * 9 + i * 2 + 1] = v1;
                }
            }
            nbar_arrive(1);        // partials(t) ready
            if (t + 1 < Tn) {
                *(float2*)(sbuf + nb * 1024 + sj0 * 8 + pq0 * 2) = preA;
                *(float2*)(sbuf + nb * 1024 + sj1 * 8 + pq0 * 2) = preB;
            }
        }
    } else {
        // ============ HH group: wait -> W_hh -> combine -> ship =============
        float c = 0.f;
        const int ct = tid - 256;
        const int cb = ct & 7, cj = (ct >> 3) & 31;
        for (int t = 0; t < Tn; ++t) {
            const int par = t & 1, nb = par ^ 1;
            {
                uint32_t mb = smb + par * 8;
                mbar_wait_cl(mb, (t >> 1) & 1);
                if (tid == 256) mbar_arm_tx(mb, 4096);
            }
            unsigned long long a0[4], a1[4];
            #pragma unroll
            for (int i = 0; i < 4; ++i) { a0[i] = 0ull; a1[i] = 0ull; }
            const float* src = hbuf + par * 1024 + (seg & 3) * 256;
            #pragma unroll
            for (int kk = 0; kk < 8; ++kk) {
                float4 w0v = wa[kk], w1v = wb[kk];
                #pragma unroll
                for (int s = 0; s < 4; ++s) {
                    const float* p = src + (kk * 4 + s) * 8;
                    ulonglong2 h0 = *(const ulonglong2*)(p);
                    ulonglong2 h1v = *(const ulonglong2*)(p + 4);
                    unsigned long long p0 = pk2(sel4(w0v, s));
                    ffma2(a0[0], p0, h0.x); ffma2(a0[1], p0, h0.y);
                    ffma2(a0[2], p0, h1v.x); ffma2(a0[3], p0, h1v.y);
                    unsigned long long p1 = pk2(sel4(w1v, s));
                    ffma2(a1[0], p1, h0.x); ffma2(a1[1], p1, h0.y);
                    ffma2(a1[2], p1, h1v.x); ffma2(a1[3], p1, h1v.y);
                }
            }
            {
                float* gp = gbuf + (par * 8 + seg) * 1152;
                float v0, v1;
                #pragma unroll
                for (int i = 0; i < 4; ++i) {
                    unpk(a0[i], v0, v1);
                    gp[r0 * 9 + i * 2] = v0; gp[r0 * 9 + i * 2 + 1] = v1;
                }
                #pragma unroll
                for (int i = 0; i < 4; ++i) {
                    unpk(a1[i], v0, v1);
                    gp[r1 * 9 + i * 2] = v0; gp[r1 * 9 + i * 2 + 1] = v1;
                }
            }
            nbar_sync(1);          // wait IH partials(t)
            {
                const float* gq = gbuf + par * 9216;
                float gv[4];
                #pragma unroll
                for (int g = 0; g < 4; ++g) {
                    int r = g * 32 + cj;
                    float s = 0.f;
                    #pragma unroll
                    for (int sg = 0; sg < 8; ++sg) s += gq[sg * 1152 + r * 9 + cb];
                    gv[g] = s;
                }
                float ii = sigm(gv[0]), ff = sigm(gv[1]), g = tanh_(gv[2]), oo = sigm(gv[3]);
                c = fmaf(ff, c, ii * g);
                float h = oo * tanh_(c);
                stage[nb * 256 + ct] = h;
                nbar_arrive(2);    // combine(t) done: release IH for t+1
                __syncwarp();
                if ((ct & 31) < 4) {
                    int dr = ct & 31;
                    fence_async_();
                    uint32_t dsto = (4 + nb * 1024 + rank * 256 + (ct & 224)) * 4;
                    uint32_t srco = (4100 + nb * 256 + (ct & 224)) * 4;
                    bulk_dsmem(base[dr] + dsto, smb + srco, 128, base[dr] + nb * 8);
                }
            }
        }
    }
    // consume the final exchange (slot 0) — exit safety + final h2 visible
    mbar_wait_cl(smb + 0, 0);

    // FC head: final h2 in hbuf slot 0 ([j][8] batch-major)
    if (rank == 0 && tid < 16) {
        int b = tid >> 1, cl = tid & 1;
        float s = fcb[cl];
        #pragma unroll
        for (int j = 0; j < 128; ++j) s = fmaf(hbuf[j * 8 + b], fcW[cl * 128 + j], s);
        out[(b0 + b) * 2 + cl] = s;
    }
}

// ---------------------------------------------------------------------------
extern "C" void kernel_launch(void* const* d_in, const int* in_sizes, int n_in,
                              void* d_out, int out_size)
{
    const float* x    = (const float*)d_in[0];
    const float* Wih0 = (const float*)d_in[1];
    const float* Whh0 = (const float*)d_in[2];
    const float* bih0 = (const float*)d_in[3];
    const float* bhh0 = (const float*)d_in[4];
    const float* Wih1 = (const float*)d_in[5];
    const float* Whh1 = (const float*)d_in[6];
    const float* bih1 = (const float*)d_in[7];
    const float* bhh1 = (const float*)d_in[8];
    const float* fcW  = (const float*)d_in[9];
    const float* fcb  = (const float*)d_in[10];
    float* out = (float*)d_out;

    cudaFuncSetAttribute(lstm_layer0, cudaFuncAttributeMaxDynamicSharedMemorySize, SMEM0_BYTES);
    cudaFuncSetAttribute(lstm_layer1, cudaFuncAttributeMaxDynamicSharedMemorySize, SMEM1_BYTES);

    lstm_layer0<<<128, 512, SMEM0_BYTES>>>(x, Wih0, Whh0, bih0, bhh0);
    lstm_layer1<<<128, 512, SMEM1_BYTES>>>(Wih1, Whh1, bih1, bhh1, fcW, fcb, out);
}

// round 13
// speedup vs baseline: 1.3010x; 1.0002x over previous
#include <cuda_runtime.h>
#include <cstdint>

#define Tn 2048

// Layer-0 hidden states, layout [T][128 j][256 b] (batch-major innermost)
__device__ float g_h1[(size_t)Tn * 128 * 256];

__device__ __forceinline__ uint32_t smem_u32(const void* p) {
    return (uint32_t)__cvta_generic_to_shared(p);
}
__device__ __forceinline__ void cluster_sync_() {
    asm volatile("barrier.cluster.arrive.aligned;" ::: "memory");
    asm volatile("barrier.cluster.wait.aligned;" ::: "memory");
}
__device__ __forceinline__ uint32_t mapa_sh(uint32_t addr, uint32_t rank) {
    uint32_t r;
    asm("mapa.shared::cluster.u32 %0, %1, %2;" : "=r"(r) : "r"(addr), "r"(rank));
    return r;
}
__device__ __forceinline__ void mbar_init(uint32_t a, uint32_t cnt) {
    asm volatile("mbarrier.init.shared.b64 [%0], %1;" :: "r"(a), "r"(cnt) : "memory");
}
__device__ __forceinline__ void mbar_arm_tx(uint32_t a, uint32_t tx) {
    asm volatile("mbarrier.arrive.expect_tx.shared.b64 _, [%0], %1;"
                 :: "r"(a), "r"(tx) : "memory");
}
__device__ __forceinline__ void mbar_wait_cl(uint32_t a, uint32_t parity) {
    asm volatile(
        "{\n\t.reg .pred P;\n\t"
        "WL_%=:\n\t"
        "mbarrier.try_wait.parity.acquire.cluster.shared::cta.b64 P, [%0], %1, 0x989680;\n\t"
        "@P bra.uni WD_%=;\n\t"
        "bra.uni WL_%=;\n\t"
        "WD_%=:\n\t}"
        :: "r"(a), "r"(parity) : "memory");
}
__device__ __forceinline__ void bulk_dsmem(uint32_t dst, uint32_t src,
                                           uint32_t bytes, uint32_t mbar) {
    asm volatile(
        "cp.async.bulk.shared::cluster.shared::cta.mbarrier::complete_tx::bytes "
        "[%0], [%1], %2, [%3];"
        :: "r"(dst), "r"(src), "r"(bytes), "r"(mbar) : "memory");
}
__device__ __forceinline__ void fence_async_() {
    asm volatile("fence.proxy.async.shared::cta;" ::: "memory");
}
// named barriers: id 1 = "A" (gate partials ready), id 2 = "B" (combine done)
__device__ __forceinline__ void nbar_sync(int id) {
    asm volatile("bar.sync %0, 512;" :: "r"(id) : "memory");
}
__device__ __forceinline__ void nbar_arrive(int id) {
    asm volatile("bar.arrive %0, 512;" :: "r"(id) : "memory");
}
__device__ __forceinline__ float sigm(float v) { return 1.0f / (1.0f + __expf(-v)); }
__device__ __forceinline__ float tanh_(float v) { return 2.0f / (1.0f + __expf(-2.0f * v)) - 1.0f; }

__device__ __forceinline__ unsigned long long pk2(float v) {
    unsigned long long r;
    asm("mov.b64 %0, {%1, %1};" : "=l"(r) : "f"(v));
    return r;
}
__device__ __forceinline__ void ffma2(unsigned long long& d, unsigned long long a,
                                      unsigned long long b) {
    asm("fma.rn.f32x2 %0, %1, %2, %0;" : "+l"(d) : "l"(a), "l"(b));
}
__device__ __forceinline__ void unpk(unsigned long long v, float& lo, float& hi) {
    asm("mov.b64 {%0, %1}, %2;" : "=f"(lo), "=f"(hi) : "l"(v));
}
__device__ __forceinline__ float sel4(float4 v, int s) {
    return (s == 0) ? v.x : (s == 1) ? v.y : (s == 2) ? v.z : v.w;
}

// ---------------------------------------------------------------------------
// Layer 0 (r9 structure + producer/consumer split): cluster of 2 CTAs x 512
// threads, 4 batches/cluster. OWN group (tid<256, segs 0-1) computes the own
// hidden slice + x-projection, runs one step ahead gated by named-bar B.
// PEER group (tid>=256, segs 2-3) waits the DSMEM exchange, computes the peer
// slice, then does the combine + exchange. Exchange protocol identical to r9.
// smem floats: mbar[4] @0, hbuf [2][128][4] @4, xbuf [2][5][4] @1028,
//              gbuf [2][4][256][5] @1068 -> 11308 floats
// ---------------------------------------------------------------------------
#define SMEM0_BYTES (11308 * 4)

__global__ void __cluster_dims__(2, 1, 1) __launch_bounds__(512, 1)
lstm_layer0(const float* __restrict__ x, const float* __restrict__ Wih,
            const float* __restrict__ Whh, const float* __restrict__ bih,
            const float* __restrict__ bhh)
{
    extern __shared__ float sm[];
    const uint32_t smb = smem_u32(sm);
    float* hbuf = sm + 4;      // [2 par][128 j][4 b]
    float* xbuf = sm + 1028;   // [2 par][5 d][4 b]
    float* gbuf = sm + 1068;   // [2 par][4 seg][256 row][5]

    const int tid  = threadIdx.x;
    const int rank = blockIdx.x & 1;
    const int b0   = (blockIdx.x >> 1) * 4;

    const int seg = tid >> 7;                 // 0..3
    const int rp  = tid & 127;
    const int r0  = rp, r1 = rp + 128;
    const int kslice = (seg < 2) ? rank : (rank ^ 1);
    const int jbase  = kslice * 64 + (seg & 1) * 32;
    const int gr0 = ((r0 >> 6) << 7) + (rank << 6) + (r0 & 63);
    const int gr1 = ((r1 >> 6) << 7) + (rank << 6) + (r1 & 63);

    float4 wa[8], wb[8];
    {
        const float4* s0 = (const float4*)(Whh + gr0 * 128 + jbase);
        const float4* s1 = (const float4*)(Whh + gr1 * 128 + jbase);
        #pragma unroll
        for (int kk = 0; kk < 8; ++kk) { wa[kk] = s0[kk]; wb[kk] = s1[kk]; }
    }
    unsigned long long wx0[5], wx1[5], bb0 = 0ull, bb1 = 0ull;
    if (seg == 0) {
        bb0 = pk2(bih[gr0] + bhh[gr0]);
        bb1 = pk2(bih[gr1] + bhh[gr1]);
        #pragma unroll
        for (int d = 0; d < 5; ++d) {
            wx0[d] = pk2(Wih[gr0 * 5 + d]);
            wx1[d] = pk2(Wih[gr1 * 5 + d]);
        }
    }

    if (tid == 0) {
        mbar_init(smb + 0, 1);
        mbar_init(smb + 8, 1);
        mbar_arm_tx(smb + 0, 1024);
        mbar_arm_tx(smb + 8, 1024);
    }
    for (int i = tid; i < 1024; i += 512) hbuf[i] = 0.f;
    if (tid < 20) {
        int b = tid / 5, d = tid % 5;
        xbuf[d * 4 + b] = x[((size_t)(b0 + b) * Tn) * 5 + d];
    }
    const uint32_t peer = mapa_sh(smb, rank ^ 1);

    __syncthreads();
    cluster_sync_();
    if (tid == 0) {
        fence_async_();
        uint32_t off = (4 + rank * 256) * 4;
        bulk_dsmem(peer + off, smb + off, 1024, peer + 0);
    }

    if (tid < 256) {
        // ============ OWN group: own-slice + x, runs ahead under bar B ======
        for (int t = 0; t < Tn; ++t) {
            const int par = t & 1, nb = par ^ 1;
            float pre = 0.f;
            if (tid < 20 && t + 1 < Tn) {
                int b = tid / 5, d = tid % 5;
                pre = x[((size_t)(b0 + b) * Tn + (t + 1)) * 5 + d];
            }
            if (t) nbar_sync(2);   // combine(t-1) done: h_self(t-1)+gbuf free
            unsigned long long a0lo = bb0, a0hi = bb0, a1lo = bb1, a1hi = bb1;
            if (seg == 0) {
                const float* xb = xbuf + par * 20;
                #pragma unroll
                for (int d = 0; d < 5; ++d) {
                    unsigned long long xlo = *(const unsigned long long*)(xb + d * 4);
                    unsigned long long xhi = *(const unsigned long long*)(xb + d * 4 + 2);
                    ffma2(a0lo, wx0[d], xlo); ffma2(a0hi, wx0[d], xhi);
                    ffma2(a1lo, wx1[d], xlo); ffma2(a1hi, wx1[d], xhi);
                }
            }
            const float* hp = hbuf + par * 512 + jbase * 4;
            #pragma unroll
            for (int kk = 0; kk < 8; ++kk) {
                float4 w0v = wa[kk], w1v = wb[kk];
                #pragma unroll
                for (int s = 0; s < 4; ++s) {
                    ulonglong2 hv = *(const ulonglong2*)(hp + (kk * 4 + s) * 4);
                    unsigned long long p0 = pk2(sel4(w0v, s));
                    ffma2(a0lo, p0, hv.x); ffma2(a0hi, p0, hv.y);
                    unsigned long long p1 = pk2(sel4(w1v, s));
                    ffma2(a1lo, p1, hv.x); ffma2(a1hi, p1, hv.y);
                }
            }
            {
                float* gp = gbuf + par * 5120 + seg * 1280;
                float v0, v1;
                unpk(a0lo, v0, v1); gp[r0 * 5 + 0] = v0; gp[r0 * 5 + 1] = v1;
                unpk(a0hi, v0, v1); gp[r0 * 5 + 2] = v0; gp[r0 * 5 + 3] = v1;
                unpk(a1lo, v0, v1); gp[r1 * 5 + 0] = v0; gp[r1 * 5 + 1] = v1;
                unpk(a1hi, v0, v1); gp[r1 * 5 + 2] = v0; gp[r1 * 5 + 3] = v1;
            }
            nbar_arrive(1);        // partials(t) ready for PEER's combine
            if (tid < 20 && t + 1 < Tn) {
                int b = tid / 5, d = tid % 5;
                xbuf[nb * 20 + d * 4 + b] = pre;
            }
        }
    } else {
        // ============ PEER group: wait -> peer slice -> combine -> ship =====
        float c = 0.f;
        const int ct = tid - 256;
        const int cb = ct & 3, cj = (ct >> 2) & 63;
        for (int t = 0; t < Tn; ++t) {
            const int par = t & 1, nb = par ^ 1;
            {
                uint32_t mb = smb + par * 8;
                mbar_wait_cl(mb, (t >> 1) & 1);
                if (tid == 256) mbar_arm_tx(mb, 1024);
            }
            unsigned long long a0lo = 0ull, a0hi = 0ull, a1lo = 0ull, a1hi = 0ull;
            const float* hp = hbuf + par * 512 + jbase * 4;
            #pragma unroll
            for (int kk = 0; kk < 8; ++kk) {
                float4 w0v = wa[kk], w1v = wb[kk];
                #pragma unroll
                for (int s = 0; s < 4; ++s) {
                    ulonglong2 hv = *(const ulonglong2*)(hp + (kk * 4 + s) * 4);
                    unsigned long long p0 = pk2(sel4(w0v, s));
                    ffma2(a0lo, p0, hv.x); ffma2(a0hi, p0, hv.y);
                    unsigned long long p1 = pk2(sel4(w1v, s));
                    ffma2(a1lo, p1, hv.x); ffma2(a1hi, p1, hv.y);
                }
            }
            {
                float* gp = gbuf + par * 5120 + seg * 1280;
                float v0, v1;
                unpk(a0lo, v0, v1); gp[r0 * 5 + 0] = v0; gp[r0 * 5 + 1] = v1;
                unpk(a0hi, v0, v1); gp[r0 * 5 + 2] = v0; gp[r0 * 5 + 3] = v1;
                unpk(a1lo, v0, v1); gp[r1 * 5 + 0] = v0; gp[r1 * 5 + 1] = v1;
                unpk(a1hi, v0, v1); gp[r1 * 5 + 2] = v0; gp[r1 * 5 + 3] = v1;
            }
            nbar_sync(1);          // wait OWN partials(t)
            {
                const float* gq = gbuf + par * 5120;
                float gv[4];
                #pragma unroll
                for (int g = 0; g < 4; ++g) {
                    int r = g * 64 + cj;
                    gv[g] = gq[r * 5 + cb] + gq[1280 + r * 5 + cb]
                          + gq[2560 + r * 5 + cb] + gq[3840 + r * 5 + cb];
                }
                float ii = sigm(gv[0]), ff = sigm(gv[1]), g = tanh_(gv[2]), oo = sigm(gv[3]);
                c = fmaf(ff, c, ii * g);
                float h = oo * tanh_(c);
                hbuf[nb * 512 + rank * 256 + ct] = h;   // self slice (STS)
                g_h1[((size_t)t * 128 + (rank << 6) + cj) * 256 + b0 + cb] = h;
                nbar_arrive(2);    // combine(t) done: release OWN for t+1
                __syncwarp();
                if ((ct & 31) == 0) {
                    fence_async_();
                    uint32_t off = (4 + nb * 512 + rank * 256 + (ct & 224)) * 4;
                    bulk_dsmem(peer + off, smb + off, 128, peer + nb * 8);
                }
            }
        }
    }
    // consume the final exchange (exit safety)
    mbar_wait_cl(smb + 0, 0);
}

// ---------------------------------------------------------------------------
// Layer 1 + FC (r9 structure + producer/consumer split): cluster of 4 CTAs x
// 512 threads, 8 batches/cluster. IH group (tid<256, segs 0-3) computes W_ih
// over gmem-prefetched h1(t) and runs one step ahead under bar B; HH group
// (tid>=256, segs 4-7) waits the h2 exchange, computes W_hh, combines, ships.
// Exchange protocol identical to r9.
// smem floats: mbar[4] @0, hbuf [2][128][8] @4, sbuf [2][128][8] @2052,
//              stage [2][256] @4100, gbuf [2][8][128][9] @4612 -> 23044 floats
// ---------------------------------------------------------------------------
#define SMEM1_BYTES (23044 * 4)

__global__ void __cluster_dims__(4, 1, 1) __launch_bounds__(512, 1)
lstm_layer1(const float* __restrict__ Wih, const float* __restrict__ Whh,
            const float* __restrict__ bih, const float* __restrict__ bhh,
            const float* __restrict__ fcW, const float* __restrict__ fcb,
            float* __restrict__ out)
{
    extern __shared__ float sm[];
    const uint32_t smb = smem_u32(sm);
    float* hbuf  = sm + 4;     // [2 par][128 j][8 b]
    float* sbuf  = sm + 2052;  // [2 par][128 j][8 b]
    float* stage = sm + 4100;  // [2 par][256]
    float* gbuf  = sm + 4612;  // [2 par][8 seg][128 row][9]

    const int tid  = threadIdx.x;
    const int rank = blockIdx.x & 3;
    const int b0   = (blockIdx.x >> 2) * 8;

    const int seg = tid >> 6;                 // 0..7
    const int rp  = tid & 63;
    const int r0  = rp, r1 = rp + 64;
    const int gr0 = ((r0 >> 5) << 7) + (rank << 5) + (r0 & 31);
    const int gr1 = ((r1 >> 5) << 7) + (rank << 5) + (r1 & 31);

    float4 wa[8], wb[8];
    {
        const float* wm = (seg < 4) ? Wih : Whh;
        const float4* s0 = (const float4*)(wm + gr0 * 128 + (seg & 3) * 32);
        const float4* s1 = (const float4*)(wm + gr1 * 128 + (seg & 3) * 32);
        #pragma unroll
        for (int kk = 0; kk < 8; ++kk) { wa[kk] = s0[kk]; wb[kk] = s1[kk]; }
    }
    unsigned long long bb0 = 0ull, bb1 = 0ull;
    if (seg == 0) {
        bb0 = pk2(bih[gr0] + bhh[gr0]);
        bb1 = pk2(bih[gr1] + bhh[gr1]);
    }

    if (tid == 0) {
        mbar_init(smb + 0, 1);
        mbar_init(smb + 8, 1);
        mbar_arm_tx(smb + 0, 4096);
        mbar_arm_tx(smb + 8, 4096);
    }
    for (int i = tid; i < 2048; i += 512) hbuf[i]  = 0.f;
    if (tid < 512) stage[tid & 511] = 0.f;

    // initial h1(0) staging: all 512 float2 slots (each thread covers 1)
    {
        int sj = tid >> 2, pq = tid & 3;
        float2 v = *(const float2*)(g_h1 + (size_t)sj * 256 + b0 + pq * 2);
        *(float2*)(sbuf + sj * 8 + pq * 2) = v;
    }
    uint32_t base[4];
    #pragma unroll
    for (int r = 0; r < 4; ++r) base[r] = mapa_sh(smb, r);

    __syncthreads();
    cluster_sync_();
    if (tid < 4) {   // prime h2(-1)=0 exchange into slot 0 / mbar 0
        fence_async_();
        bulk_dsmem(base[tid] + (4 + rank * 256) * 4, smb + 4100 * 4,
                   1024, base[tid] + 0);
    }

    if (tid < 256) {
        // ============ IH group: W_ih over prefetched h1, runs ahead =========
        const int sj0 = tid >> 2, pq0 = tid & 3;        // covers idx tid
        const int sj1 = sj0 + 64;                       // covers idx tid+256
        for (int t = 0; t < Tn; ++t) {
            const int par = t & 1, nb = par ^ 1;
            float2 preA = make_float2(0.f, 0.f), preB = make_float2(0.f, 0.f);
            if (t + 1 < Tn) {
                preA = *(const float2*)(g_h1 + ((size_t)(t + 1) * 128 + sj0) * 256 + b0 + pq0 * 2);
                preB = *(const float2*)(g_h1 + ((size_t)(t + 1) * 128 + sj1) * 256 + b0 + pq0 * 2);
            }
            if (t) nbar_sync(2);   // combine(t-1) done: gbuf[par] free
            unsigned long long a0[4], a1[4];
            #pragma unroll
            for (int i = 0; i < 4; ++i) { a0[i] = bb0; a1[i] = bb1; }
            const float* src = sbuf + par * 1024 + (seg & 3) * 256;
            #pragma unroll
            for (int kk = 0; kk < 8; ++kk) {
                float4 w0v = wa[kk], w1v = wb[kk];
                #pragma unroll
                for (int s = 0; s < 4; ++s) {
                    const float* p = src + (kk * 4 + s) * 8;
                    ulonglong2 h0 = *(const ulonglong2*)(p);
                    ulonglong2 h1v = *(const ulonglong2*)(p + 4);
                    unsigned long long p0 = pk2(sel4(w0v, s));
                    ffma2(a0[0], p0, h0.x); ffma2(a0[1], p0, h0.y);
                    ffma2(a0[2], p0, h1v.x); ffma2(a0[3], p0, h1v.y);
                    unsigned long long p1 = pk2(sel4(w1v, s));
                    ffma2(a1[0], p1, h0.x); ffma2(a1[1], p1, h0.y);
                    ffma2(a1[2], p1, h1v.x); ffma2(a1[3], p1, h1v.y);
                }
            }
            {
                float* gp = gbuf + (par * 8 + seg) * 1152;
                float v0, v1;
                #pragma unroll
                for (int i = 0; i < 4; ++i) {
                    unpk(a0[i], v0, v1);
                    gp[r0 * 9 + i * 2] = v0; gp[r0 * 9 + i * 2 + 1] = v1;
                }
                #pragma unroll
                for (int i = 0; i < 4; ++i) {
                    unpk(a1[i], v0, v1);
                    gp[r1 * 9 + i * 2] = v0; gp[r1 * 9 + i * 2 + 1] = v1;
                }
            }
            nbar_arrive(1);        // partials(t) ready
            if (t + 1 < Tn) {
                *(float2*)(sbuf + nb * 1024 + sj0 * 8 + pq0 * 2) = preA;
                *(float2*)(sbuf + nb * 1024 + sj1 * 8 + pq0 * 2) = preB;
            }
        }
    } else {
        // ============ HH group: wait -> W_hh -> combine -> ship =============
        float c = 0.f;
        const int ct = tid - 256;
        const int cb = ct & 7, cj = (ct >> 3) & 31;
        for (int t = 0; t < Tn; ++t) {
            const int par = t & 1, nb = par ^ 1;
            {
                uint32_t mb = smb + par * 8;
                mbar_wait_cl(mb, (t >> 1) & 1);
                if (tid == 256) mbar_arm_tx(mb, 4096);
            }
            unsigned long long a0[4], a1[4];
            #pragma unroll
            for (int i = 0; i < 4; ++i) { a0[i] = 0ull; a1[i] = 0ull; }
            const float* src = hbuf + par * 1024 + (seg & 3) * 256;
            #pragma unroll
            for (int kk = 0; kk < 8; ++kk) {
                float4 w0v = wa[kk], w1v = wb[kk];
                #pragma unroll
                for (int s = 0; s < 4; ++s) {
                    const float* p = src + (kk * 4 + s) * 8;
                    ulonglong2 h0 = *(const ulonglong2*)(p);
                    ulonglong2 h1v = *(const ulonglong2*)(p + 4);
                    unsigned long long p0 = pk2(sel4(w0v, s));
                    ffma2(a0[0], p0, h0.x); ffma2(a0[1], p0, h0.y);
                    ffma2(a0[2], p0, h1v.x); ffma2(a0[3], p0, h1v.y);
                    unsigned long long p1 = pk2(sel4(w1v, s));
                    ffma2(a1[0], p1, h0.x); ffma2(a1[1], p1, h0.y);
                    ffma2(a1[2], p1, h1v.x); ffma2(a1[3], p1, h1v.y);
                }
            }
            {
                float* gp = gbuf + (par * 8 + seg) * 1152;
                float v0, v1;
                #pragma unroll
                for (int i = 0; i < 4; ++i) {
                    unpk(a0[i], v0, v1);
                    gp[r0 * 9 + i * 2] = v0; gp[r0 * 9 + i * 2 + 1] = v1;
                }
                #pragma unroll
                for (int i = 0; i < 4; ++i) {
                    unpk(a1[i], v0, v1);
                    gp[r1 * 9 + i * 2] = v0; gp[r1 * 9 + i * 2 + 1] = v1;
                }
            }
            nbar_sync(1);          // wait IH partials(t)
            {
                const float* gq = gbuf + par * 9216;
                float gv[4];
                #pragma unroll
                for (int g = 0; g < 4; ++g) {
                    int r = g * 32 + cj;
                    float s = 0.f;
                    #pragma unroll
                    for (int sg = 0; sg < 8; ++sg) s += gq[sg * 1152 + r * 9 + cb];
                    gv[g] = s;
                }
                float ii = sigm(gv[0]), ff = sigm(gv[1]), g = tanh_(gv[2]), oo = sigm(gv[3]);
                c = fmaf(ff, c, ii * g);
                float h = oo * tanh_(c);
                stage[nb * 256 + ct] = h;
                nbar_arrive(2);    // combine(t) done: release IH for t+1
                __syncwarp();
                if ((ct & 31) < 4) {
                    int dr = ct & 31;
                    fence_async_();
                    uint32_t dsto = (4 + nb * 1024 + rank * 256 + (ct & 224)) * 4;
                    uint32_t srco = (4100 + nb * 256 + (ct & 224)) * 4;
                    bulk_dsmem(base[dr] + dsto, smb + srco, 128, base[dr] + nb * 8);
                }
            }
        }
    }
    // consume the final exchange (slot 0) — exit safety + final h2 visible
    mbar_wait_cl(smb + 0, 0);

    // FC head: final h2 in hbuf slot 0 ([j][8] batch-major)
    if (rank == 0 && tid < 16) {
        int b = tid >> 1, cl = tid & 1;
        float s = fcb[cl];
        #pragma unroll
        for (int j = 0; j < 128; ++j) s = fmaf(hbuf[j * 8 + b], fcW[cl * 128 + j], s);
        out[(b0 + b) * 2 + cl] = s;
    }
}

// ---------------------------------------------------------------------------
extern "C" void kernel_launch(void* const* d_in, const int* in_sizes, int n_in,
                              void* d_out, int out_size)
{
    const float* x    = (const float*)d_in[0];
    const float* Wih0 = (const float*)d_in[1];
    const float* Whh0 = (const float*)d_in[2];
    const float* bih0 = (const float*)d_in[3];
    const float* bhh0 = (const float*)d_in[4];
    const float* Wih1 = (const float*)d_in[5];
    const float* Whh1 = (const float*)d_in[6];
    const float* bih1 = (const float*)d_in[7];
    const float* bhh1 = (const float*)d_in[8];
    const float* fcW  = (const float*)d_in[9];
    const float* fcb  = (const float*)d_in[10];
    float* out = (float*)d_out;

    cudaFuncSetAttribute(lstm_layer0, cudaFuncAttributeMaxDynamicSharedMemorySize, SMEM0_BYTES);
    cudaFuncSetAttribute(lstm_layer1, cudaFuncAttributeMaxDynamicSharedMemorySize, SMEM1_BYTES);

    lstm_layer0<<<128, 512, SMEM0_BYTES>>>(x, Wih0, Whh0, bih0, bhh0);
    lstm_layer1<<<128, 512, SMEM1_BYTES>>>(Wih1, Whh1, bih1, bhh1, fcW, fcb, out);
}

// round 14
// speedup vs baseline: 1.3800x; 1.0607x over previous
#include <cuda_runtime.h>
#include <cstdint>

#define Tn 2048

// Layer-0 hidden states, layout [T][128 j][256 b] (batch-major innermost)
__device__ float g_h1[(size_t)Tn * 128 * 256];

__device__ __forceinline__ uint32_t smem_u32(const void* p) {
    return (uint32_t)__cvta_generic_to_shared(p);
}
__device__ __forceinline__ void cluster_sync_() {
    asm volatile("barrier.cluster.arrive.aligned;" ::: "memory");
    asm volatile("barrier.cluster.wait.aligned;" ::: "memory");
}
__device__ __forceinline__ uint32_t mapa_sh(uint32_t addr, uint32_t rank) {
    uint32_t r;
    asm("mapa.shared::cluster.u32 %0, %1, %2;" : "=r"(r) : "r"(addr), "r"(rank));
    return r;
}
__device__ __forceinline__ void mbar_init(uint32_t a, uint32_t cnt) {
    asm volatile("mbarrier.init.shared.b64 [%0], %1;" :: "r"(a), "r"(cnt) : "memory");
}
__device__ __forceinline__ void mbar_arm_tx(uint32_t a, uint32_t tx) {
    asm volatile("mbarrier.arrive.expect_tx.shared.b64 _, [%0], %1;"
                 :: "r"(a), "r"(tx) : "memory");
}
__device__ __forceinline__ void mbar_wait_cl(uint32_t a, uint32_t parity) {
    asm volatile(
        "{\n\t.reg .pred P;\n\t"
        "WL_%=:\n\t"
        "mbarrier.try_wait.parity.acquire.cluster.shared::cta.b64 P, [%0], %1, 0x989680;\n\t"
        "@P bra.uni WD_%=;\n\t"
        "bra.uni WL_%=;\n\t"
        "WD_%=:\n\t}"
        :: "r"(a), "r"(parity) : "memory");
}
__device__ __forceinline__ void bulk_dsmem(uint32_t dst, uint32_t src,
                                           uint32_t bytes, uint32_t mbar) {
    asm volatile(
        "cp.async.bulk.shared::cluster.shared::cta.mbarrier::complete_tx::bytes "
        "[%0], [%1], %2, [%3];"
        :: "r"(dst), "r"(src), "r"(bytes), "r"(mbar) : "memory");
}
__device__ __forceinline__ void fence_async_() {
    asm volatile("fence.proxy.async.shared::cta;" ::: "memory");
}
__device__ __forceinline__ void nbar_sync(int id, int cnt) {
    asm volatile("bar.sync %0, %1;" :: "r"(id), "r"(cnt) : "memory");
}
__device__ __forceinline__ void nbar_arrive(int id, int cnt) {
    asm volatile("bar.arrive %0, %1;" :: "r"(id), "r"(cnt) : "memory");
}
__device__ __forceinline__ float sigm(float v) { return 1.0f / (1.0f + __expf(-v)); }
__device__ __forceinline__ float tanh_(float v) { return 2.0f / (1.0f + __expf(-2.0f * v)) - 1.0f; }

__device__ __forceinline__ unsigned long long pk2(float v) {
    unsigned long long r;
    asm("mov.b64 %0, {%1, %1};" : "=l"(r) : "f"(v));
    return r;
}
__device__ __forceinline__ void ffma2(unsigned long long& d, unsigned long long a,
                                      unsigned long long b) {
    asm("fma.rn.f32x2 %0, %1, %2, %0;" : "+l"(d) : "l"(a), "l"(b));
}
__device__ __forceinline__ void unpk(unsigned long long v, float& lo, float& hi) {
    asm("mov.b64 {%0, %1}, %2;" : "=f"(lo), "=f"(hi) : "l"(v));
}
__device__ __forceinline__ float sel4(float4 v, int s) {
    return (s == 0) ? v.x : (s == 1) ? v.y : (s == 2) ? v.z : v.w;
}

// ---------------------------------------------------------------------------
// Layer 0 — UNCHANGED from r13 (proven at 6800): cluster of 2 CTAs x 512
// threads, OWN group (segs 0-1) ahead under named-bar B, PEER group (segs
// 2-3) waits exchange, computes, combines, ships.
// smem floats: mbar[4] @0, hbuf [2][128][4] @4, xbuf [2][5][4] @1028,
//              gbuf [2][4][256][5] @1068 -> 11308 floats
// ---------------------------------------------------------------------------
#define SMEM0_BYTES (11308 * 4)

__global__ void __cluster_dims__(2, 1, 1) __launch_bounds__(512, 1)
lstm_layer0(const float* __restrict__ x, const float* __restrict__ Wih,
            const float* __restrict__ Whh, const float* __restrict__ bih,
            const float* __restrict__ bhh)
{
    extern __shared__ float sm[];
    const uint32_t smb = smem_u32(sm);
    float* hbuf = sm + 4;      // [2 par][128 j][4 b]
    float* xbuf = sm + 1028;   // [2 par][5 d][4 b]
    float* gbuf = sm + 1068;   // [2 par][4 seg][256 row][5]

    const int tid  = threadIdx.x;
    const int rank = blockIdx.x & 1;
    const int b0   = (blockIdx.x >> 1) * 4;

    const int seg = tid >> 7;                 // 0..3
    const int rp  = tid & 127;
    const int r0  = rp, r1 = rp + 128;
    const int kslice = (seg < 2) ? rank : (rank ^ 1);
    const int jbase  = kslice * 64 + (seg & 1) * 32;
    const int gr0 = ((r0 >> 6) << 7) + (rank << 6) + (r0 & 63);
    const int gr1 = ((r1 >> 6) << 7) + (rank << 6) + (r1 & 63);

    float4 wa[8], wb[8];
    {
        const float4* s0 = (const float4*)(Whh + gr0 * 128 + jbase);
        const float4* s1 = (const float4*)(Whh + gr1 * 128 + jbase);
        #pragma unroll
        for (int kk = 0; kk < 8; ++kk) { wa[kk] = s0[kk]; wb[kk] = s1[kk]; }
    }
    unsigned long long wx0[5], wx1[5], bb0 = 0ull, bb1 = 0ull;
    if (seg == 0) {
        bb0 = pk2(bih[gr0] + bhh[gr0]);
        bb1 = pk2(bih[gr1] + bhh[gr1]);
        #pragma unroll
        for (int d = 0; d < 5; ++d) {
            wx0[d] = pk2(Wih[gr0 * 5 + d]);
            wx1[d] = pk2(Wih[gr1 * 5 + d]);
        }
    }

    if (tid == 0) {
        mbar_init(smb + 0, 1);
        mbar_init(smb + 8, 1);
        mbar_arm_tx(smb + 0, 1024);
        mbar_arm_tx(smb + 8, 1024);
    }
    for (int i = tid; i < 1024; i += 512) hbuf[i] = 0.f;
    if (tid < 20) {
        int b = tid / 5, d = tid % 5;
        xbuf[d * 4 + b] = x[((size_t)(b0 + b) * Tn) * 5 + d];
    }
    const uint32_t peer = mapa_sh(smb, rank ^ 1);

    __syncthreads();
    cluster_sync_();
    if (tid == 0) {
        fence_async_();
        uint32_t off = (4 + rank * 256) * 4;
        bulk_dsmem(peer + off, smb + off, 1024, peer + 0);
    }

    if (tid < 256) {
        // OWN group: own-slice + x, runs ahead under bar B
        for (int t = 0; t < Tn; ++t) {
            const int par = t & 1, nb = par ^ 1;
            float pre = 0.f;
            if (tid < 20 && t + 1 < Tn) {
                int b = tid / 5, d = tid % 5;
                pre = x[((size_t)(b0 + b) * Tn + (t + 1)) * 5 + d];
            }
            if (t) nbar_sync(2, 512);
            unsigned long long a0lo = bb0, a0hi = bb0, a1lo = bb1, a1hi = bb1;
            if (seg == 0) {
                const float* xb = xbuf + par * 20;
                #pragma unroll
                for (int d = 0; d < 5; ++d) {
                    unsigned long long xlo = *(const unsigned long long*)(xb + d * 4);
                    unsigned long long xhi = *(const unsigned long long*)(xb + d * 4 + 2);
                    ffma2(a0lo, wx0[d], xlo); ffma2(a0hi, wx0[d], xhi);
                    ffma2(a1lo, wx1[d], xlo); ffma2(a1hi, wx1[d], xhi);
                }
            }
            const float* hp = hbuf + par * 512 + jbase * 4;
            #pragma unroll
            for (int kk = 0; kk < 8; ++kk) {
                float4 w0v = wa[kk], w1v = wb[kk];
                #pragma unroll
                for (int s = 0; s < 4; ++s) {
                    ulonglong2 hv = *(const ulonglong2*)(hp + (kk * 4 + s) * 4);
                    unsigned long long p0 = pk2(sel4(w0v, s));
                    ffma2(a0lo, p0, hv.x); ffma2(a0hi, p0, hv.y);
                    unsigned long long p1 = pk2(sel4(w1v, s));
                    ffma2(a1lo, p1, hv.x); ffma2(a1hi, p1, hv.y);
                }
            }
            {
                float* gp = gbuf + par * 5120 + seg * 1280;
                float v0, v1;
                unpk(a0lo, v0, v1); gp[r0 * 5 + 0] = v0; gp[r0 * 5 + 1] = v1;
                unpk(a0hi, v0, v1); gp[r0 * 5 + 2] = v0; gp[r0 * 5 + 3] = v1;
                unpk(a1lo, v0, v1); gp[r1 * 5 + 0] = v0; gp[r1 * 5 + 1] = v1;
                unpk(a1hi, v0, v1); gp[r1 * 5 + 2] = v0; gp[r1 * 5 + 3] = v1;
            }
            nbar_arrive(1, 512);
            if (tid < 20 && t + 1 < Tn) {
                int b = tid / 5, d = tid % 5;
                xbuf[nb * 20 + d * 4 + b] = pre;
            }
        }
    } else {
        // PEER group: wait -> peer slice -> combine -> ship
        float c = 0.f;
        const int ct = tid - 256;
        const int cb = ct & 3, cj = (ct >> 2) & 63;
        for (int t = 0; t < Tn; ++t) {
            const int par = t & 1, nb = par ^ 1;
            {
                uint32_t mb = smb + par * 8;
                mbar_wait_cl(mb, (t >> 1) & 1);
                if (tid == 256) mbar_arm_tx(mb, 1024);
            }
            unsigned long long a0lo = 0ull, a0hi = 0ull, a1lo = 0ull, a1hi = 0ull;
            const float* hp = hbuf + par * 512 + jbase * 4;
            #pragma unroll
            for (int kk = 0; kk < 8; ++kk) {
                float4 w0v = wa[kk], w1v = wb[kk];
                #pragma unroll
                for (int s = 0; s < 4; ++s) {
                    ulonglong2 hv = *(const ulonglong2*)(hp + (kk * 4 + s) * 4);
                    unsigned long long p0 = pk2(sel4(w0v, s));
                    ffma2(a0lo, p0, hv.x); ffma2(a0hi, p0, hv.y);
                    unsigned long long p1 = pk2(sel4(w1v, s));
                    ffma2(a1lo, p1, hv.x); ffma2(a1hi, p1, hv.y);
                }
            }
            {
                float* gp = gbuf + par * 5120 + seg * 1280;
                float v0, v1;
                unpk(a0lo, v0, v1); gp[r0 * 5 + 0] = v0; gp[r0 * 5 + 1] = v1;
                unpk(a0hi, v0, v1); gp[r0 * 5 + 2] = v0; gp[r0 * 5 + 3] = v1;
                unpk(a1lo, v0, v1); gp[r1 * 5 + 0] = v0; gp[r1 * 5 + 1] = v1;
                unpk(a1hi, v0, v1); gp[r1 * 5 + 2] = v0; gp[r1 * 5 + 3] = v1;
            }
            nbar_sync(1, 512);
            {
                const float* gq = gbuf + par * 5120;
                float gv[4];
                #pragma unroll
                for (int g = 0; g < 4; ++g) {
                    int r = g * 64 + cj;
                    gv[g] = gq[r * 5 + cb] + gq[1280 + r * 5 + cb]
                          + gq[2560 + r * 5 + cb] + gq[3840 + r * 5 + cb];
                }
                float ii = sigm(gv[0]), ff = sigm(gv[1]), g = tanh_(gv[2]), oo = sigm(gv[3]);
                c = fmaf(ff, c, ii * g);
                float h = oo * tanh_(c);
                hbuf[nb * 512 + rank * 256 + ct] = h;   // self slice (STS)
                g_h1[((size_t)t * 128 + (rank << 6) + cj) * 256 + b0 + cb] = h;
                nbar_arrive(2, 512);
                __syncwarp();
                if ((ct & 31) == 0) {
                    fence_async_();
                    uint32_t off = (4 + nb * 512 + rank * 256 + (ct & 224)) * 4;
                    bulk_dsmem(peer + off, smb + off, 128, peer + nb * 8);
                }
            }
        }
    }
    mbar_wait_cl(smb + 0, 0);   // exit safety
}

// ---------------------------------------------------------------------------
// Layer 1 + FC (r13 + chain cuts): cluster of 4 CTAs x 512 threads.
//  - IH group (tid<256, segs 0-3): W_ih over gmem-prefetched h1, up to TWO
//    steps ahead via paritied lagged bar-B (ids 3,4): combine(t) arrives
//    3+(t&1); IH at t (t>=2) syncs 3+(t&1), consuming combine(t-2).
//  - HH group (tid>=256, segs 4-7 <-> h2 slice 0-3): own slice (slice==rank)
//    read from local stage (no wait, ordered by HH-only bar 5); remote slices
//    each wait a per-source mbarrier [par][src] (tx=1024).
//  - bar-A paritied too (ids 1,2).
// smem floats: mbars[16] @0 ([2 par][4 src] x 8B), hbuf [2][128][8] @16,
//              sbuf [2][128][8] @2064, stage [2][256] @4112,
//              gbuf [2][8][128][9] @4624 -> 23056 floats
// ---------------------------------------------------------------------------
#define SMEM1_BYTES (23056 * 4)

__global__ void __cluster_dims__(4, 1, 1) __launch_bounds__(512, 1)
lstm_layer1(const float* __restrict__ Wih, const float* __restrict__ Whh,
            const float* __restrict__ bih, const float* __restrict__ bhh,
            const float* __restrict__ fcW, const float* __restrict__ fcb,
            float* __restrict__ out)
{
    extern __shared__ float sm[];
    const uint32_t smb = smem_u32(sm);
    float* hbuf  = sm + 16;    // [2 par][128 j][8 b]
    float* sbuf  = sm + 2064;  // [2 par][128 j][8 b]
    float* stage = sm + 4112;  // [2 par][32 j][8 b] own h2 slice
    float* gbuf  = sm + 4624;  // [2 par][8 seg][128 row][9]

    const int tid  = threadIdx.x;
    const int rank = blockIdx.x & 3;
    const int b0   = (blockIdx.x >> 2) * 8;

    const int seg = tid >> 6;                 // 0..7
    const int rp  = tid & 63;
    const int r0  = rp, r1 = rp + 64;
    const int gr0 = ((r0 >> 5) << 7) + (rank << 5) + (r0 & 31);
    const int gr1 = ((r1 >> 5) << 7) + (rank << 5) + (r1 & 31);

    float4 wa[8], wb[8];
    {
        const float* wm = (seg < 4) ? Wih : Whh;
        const float4* s0 = (const float4*)(wm + gr0 * 128 + (seg & 3) * 32);
        const float4* s1 = (const float4*)(wm + gr1 * 128 + (seg & 3) * 32);
        #pragma unroll
        for (int kk = 0; kk < 8; ++kk) { wa[kk] = s0[kk]; wb[kk] = s1[kk]; }
    }
    unsigned long long bb0 = 0ull, bb1 = 0ull;
    if (seg == 0) {
        bb0 = pk2(bih[gr0] + bhh[gr0]);
        bb1 = pk2(bih[gr1] + bhh[gr1]);
    }

    if (tid == 0) {   // 8 mbars: [par][src]; arm only src != rank (tx 1024)
        #pragma unroll
        for (int p = 0; p < 2; ++p)
            #pragma unroll
            for (int s = 0; s < 4; ++s) {
                uint32_t mb = smb + p * 32 + s * 8;
                mbar_init(mb, 1);
                if (s != rank) mbar_arm_tx(mb, 1024);
            }
    }
    for (int i = tid; i < 2048; i += 512) hbuf[i] = 0.f;
    if (tid < 512) stage[tid] = 0.f;

    // initial h1(0) staging (each thread covers one float2)
    {
        int sj = tid >> 2, pq = tid & 3;
        float2 v = *(const float2*)(g_h1 + (size_t)sj * 256 + b0 + pq * 2);
        *(float2*)(sbuf + sj * 8 + pq * 2) = v;
    }
    uint32_t base[4];
    #pragma unroll
    for (int r = 0; r < 4; ++r) base[r] = mapa_sh(smb, r);

    __syncthreads();
    cluster_sync_();
    // prime h2(-1)=0: ship zeroed 1024B slice into the 3 remotes' [par0][rank]
    if (tid < 3) {
        int dr = tid + (tid >= rank);
        fence_async_();
        bulk_dsmem(base[dr] + (16 + rank * 256) * 4, smb + 4112 * 4,
                   1024, base[dr] + rank * 8);
    }

    if (tid < 256) {
        // ===== IH group: up to 2 steps ahead (lagged paritied bar-B) =======
        const int sj0 = tid >> 2, pq0 = tid & 3;
        const int sj1 = sj0 + 64;
        for (int t = 0; t < Tn; ++t) {
            const int par = t & 1, nb = par ^ 1;
            float2 preA = make_float2(0.f, 0.f), preB = make_float2(0.f, 0.f);
            if (t + 1 < Tn) {
                preA = *(const float2*)(g_h1 + ((size_t)(t + 1) * 128 + sj0) * 256 + b0 + pq0 * 2);
                preB = *(const float2*)(g_h1 + ((size_t)(t + 1) * 128 + sj1) * 256 + b0 + pq0 * 2);
            }
            if (t >= 2) nbar_sync(3 + par, 512);   // combine(t-2) done
            unsigned long long a0[4], a1[4];
            #pragma unroll
            for (int i = 0; i < 4; ++i) { a0[i] = bb0; a1[i] = bb1; }
            const float* src = sbuf + par * 1024 + (seg & 3) * 256;
            #pragma unroll
            for (int kk = 0; kk < 8; ++kk) {
                float4 w0v = wa[kk], w1v = wb[kk];
                #pragma unroll
                for (int s = 0; s < 4; ++s) {
                    const float* p = src + (kk * 4 + s) * 8;
                    ulonglong2 h0 = *(const ulonglong2*)(p);
                    ulonglong2 h1v = *(const ulonglong2*)(p + 4);
                    unsigned long long p0 = pk2(sel4(w0v, s));
                    ffma2(a0[0], p0, h0.x); ffma2(a0[1], p0, h0.y);
                    ffma2(a0[2], p0, h1v.x); ffma2(a0[3], p0, h1v.y);
                    unsigned long long p1 = pk2(sel4(w1v, s));
                    ffma2(a1[0], p1, h0.x); ffma2(a1[1], p1, h0.y);
                    ffma2(a1[2], p1, h1v.x); ffma2(a1[3], p1, h1v.y);
                }
            }
            {
                float* gp = gbuf + (par * 8 + seg) * 1152;
                float v0, v1;
                #pragma unroll
                for (int i = 0; i < 4; ++i) {
                    unpk(a0[i], v0, v1);
                    gp[r0 * 9 + i * 2] = v0; gp[r0 * 9 + i * 2 + 1] = v1;
                }
                #pragma unroll
                for (int i = 0; i < 4; ++i) {
                    unpk(a1[i], v0, v1);
                    gp[r1 * 9 + i * 2] = v0; gp[r1 * 9 + i * 2 + 1] = v1;
                }
            }
            nbar_arrive(1 + par, 512);             // partials(t) ready
            if (t + 1 < Tn) {
                *(float2*)(sbuf + nb * 1024 + sj0 * 8 + pq0 * 2) = preA;
                *(float2*)(sbuf + nb * 1024 + sj1 * 8 + pq0 * 2) = preB;
            }
        }
    } else {
        // ===== HH group: per-source waits -> W_hh -> combine -> ship =======
        float c = 0.f;
        const int ct = tid - 256;
        const int cb = ct & 7, cj = (ct >> 3) & 31;
        const int slice = seg - 4;                 // 0..3
        for (int t = 0; t < Tn; ++t) {
            const int par = t & 1, nb = par ^ 1;
            const float* src;
            if (slice == rank) {
                src = stage + par * 256;           // own slice: local, no wait
            } else {
                uint32_t mb = smb + par * 32 + slice * 8;
                mbar_wait_cl(mb, (t >> 1) & 1);
                if ((tid & 63) == 0) mbar_arm_tx(mb, 1024);
                src = hbuf + par * 1024 + slice * 256;
            }
            unsigned long long a0[4], a1[4];
            #pragma unroll
            for (int i = 0; i < 4; ++i) { a0[i] = 0ull; a1[i] = 0ull; }
            #pragma unroll
            for (int kk = 0; kk < 8; ++kk) {
                float4 w0v = wa[kk], w1v = wb[kk];
                #pragma unroll
                for (int s = 0; s < 4; ++s) {
                    const float* p = src + (kk * 4 + s) * 8;
                    ulonglong2 h0 = *(const ulonglong2*)(p);
                    ulonglong2 h1v = *(const ulonglong2*)(p + 4);
                    unsigned long long p0 = pk2(sel4(w0v, s));
                    ffma2(a0[0], p0, h0.x); ffma2(a0[1], p0, h0.y);
                    ffma2(a0[2], p0, h1v.x); ffma2(a0[3], p0, h1v.y);
                    unsigned long long p1 = pk2(sel4(w1v, s));
                    ffma2(a1[0], p1, h0.x); ffma2(a1[1], p1, h0.y);
                    ffma2(a1[2], p1, h1v.x); ffma2(a1[3], p1, h1v.y);
                }
            }
            {
                float* gp = gbuf + (par * 8 + seg) * 1152;
                float v0, v1;
                #pragma unroll
                for (int i = 0; i < 4; ++i) {
                    unpk(a0[i], v0, v1);
                    gp[r0 * 9 + i * 2] = v0; gp[r0 * 9 + i * 2 + 1] = v1;
                }
                #pragma unroll
                for (int i = 0; i < 4; ++i) {
                    unpk(a1[i], v0, v1);
                    gp[r1 * 9 + i * 2] = v0; gp[r1 * 9 + i * 2 + 1] = v1;
                }
            }
            nbar_sync(1 + par, 512);               // wait IH partials(t)
            {
                const float* gq = gbuf + par * 9216;
                float gv[4];
                #pragma unroll
                for (int g = 0; g < 4; ++g) {
                    int r = g * 32 + cj;
                    float s = 0.f;
                    #pragma unroll
                    for (int sg = 0; sg < 8; ++sg) s += gq[sg * 1152 + r * 9 + cb];
                    gv[g] = s;
                }
                nbar_arrive(3 + par, 512);         // gbuf[par] free for IH(t+2)
                float ii = sigm(gv[0]), ff = sigm(gv[1]), g = tanh_(gv[2]), oo = sigm(gv[3]);
                c = fmaf(ff, c, ii * g);
                float h = oo * tanh_(c);
                stage[nb * 256 + ct] = h;
                __syncwarp();
                if ((ct & 31) < 3) {               // ship only to the 3 remotes
                    int l = ct & 31;
                    int dr = l + (l >= rank);
                    fence_async_();
                    uint32_t dsto = (16 + nb * 1024 + rank * 256 + (ct & 224)) * 4;
                    uint32_t srco = (4112 + nb * 256 + (ct & 224)) * 4;
                    bulk_dsmem(base[dr] + dsto, smb + srco, 128,
                               base[dr] + nb * 32 + rank * 8);
                }
                nbar_sync(5, 256);                 // HH-only: stage visible
            }
        }
        // consume final inbound exchange (phase 0) — exit safety
        if (slice != rank) mbar_wait_cl(smb + slice * 8, 0);
    }
    __syncthreads();

    // FC head: final h2 = remote slices in hbuf[par 0] + own slice in stage[0]
    if (rank == 0 && tid < 16) {
        int b = tid >> 1, cl = tid & 1;
        float s = fcb[cl];
        #pragma unroll
        for (int j = 0; j < 128; ++j) {
            float hv = ((j >> 5) == rank) ? stage[(j & 31) * 8 + b]
                                          : hbuf[j * 8 + b];
            s = fmaf(hv, fcW[cl * 128 + j], s);
        }
        out[(b0 + b) * 2 + cl] = s;
    }
}

// ---------------------------------------------------------------------------
extern "C" void kernel_launch(void* const* d_in, const int* in_sizes, int n_in,
                              void* d_out, int out_size)
{
    const float* x    = (const float*)d_in[0];
    const float* Wih0 = (const float*)d_in[1];
    const float* Whh0 = (const float*)d_in[2];
    const float* bih0 = (const float*)d_in[3];
    const float* bhh0 = (const float*)d_in[4];
    const float* Wih1 = (const float*)d_in[5];
    const float* Whh1 = (const float*)d_in[6];
    const float* bih1 = (const float*)d_in[7];
    const float* bhh1 = (const float*)d_in[8];
    const float* fcW  = (const float*)d_in[9];
    const float* fcb  = (const float*)d_in[10];
    float* out = (float*)d_out;

    cudaFuncSetAttribute(lstm_layer0, cudaFuncAttributeMaxDynamicSharedMemorySize, SMEM0_BYTES);
    cudaFuncSetAttribute(lstm_layer1, cudaFuncAttributeMaxDynamicSharedMemorySize, SMEM1_BYTES);

    lstm_layer0<<<128, 512, SMEM0_BYTES>>>(x, Wih0, Whh0, bih0, bhh0);
    lstm_layer1<<<128, 512, SMEM1_BYTES>>>(Wih1, Whh1, bih1, bhh1, fcW, fcb, out);
}